// round 2
// baseline (speedup 1.0000x reference)
#include <cuda_runtime.h>
#include <math.h>

// Problem constants
namespace {
constexpr int Bn = 4, Ln = 2048, En = 1024, Vn = 64, NTn = 2016;
constexpr int Mn = Bn * Ln;  // 8192 tokens
}

// Scratch (static device globals — no runtime allocation)
__device__ float g_act[(size_t)Mn * En];      // gelu(dense) output, 32 MB
__device__ float g_hidden[(size_t)Mn * En];   // LayerNorm output,   32 MB
__device__ float g_theta[(size_t)Mn * NTn];   // softplus(Theta),    66 MB

__device__ __forceinline__ float gelu_exact(float x) {
    return 0.5f * x * (1.0f + erff(x * 0.7071067811865476f));
}
__device__ __forceinline__ float softplus_f(float x) {
    if (x > 20.0f) return x;
    return log1pf(expf(x));
}

// ---------------------------------------------------------------------------
// C[m,n] = act( dot(A[m,:], B[n,:]) + bias[n] )
// A: M x K row-major, B: N x K row-major (NT GEMM). M,K multiples of 128/16.
// N may be ragged (2016) -> guarded.
// ---------------------------------------------------------------------------
template <int ACT>  // 0 none, 1 gelu, 2 softplus
__global__ __launch_bounds__(256, 2)
void gemm_nt_kernel(const float* __restrict__ A, const float* __restrict__ B,
                    const float* __restrict__ bias, float* __restrict__ C,
                    int M, int N, int K) {
    constexpr int BM = 128, BN = 128, BK = 16, PAD = 4;
    __shared__ float As[BK][BM + PAD];
    __shared__ float Bs[BK][BN + PAD];

    const int tid = threadIdx.x;
    const int m0 = blockIdx.y * BM;
    const int n0 = blockIdx.x * BN;
    const int tx = tid & 15;
    const int ty = tid >> 4;
    const int tm = ty * 8;
    const int tn = tx * 8;

    // load mapping: each thread loads 2 float4 from A and 2 from B per tile
    const int r0 = tid >> 2;        // row 0..63 (second load: +64)
    const int c4 = (tid & 3) * 4;   // float offset within 16-wide K slab

    float acc[8][8];
#pragma unroll
    for (int i = 0; i < 8; i++)
#pragma unroll
        for (int j = 0; j < 8; j++) acc[i][j] = 0.0f;

    float4 ra0, ra1, rb0, rb1;
    const int NKT = K / BK;

    // prologue: load tile 0
    ra0 = *(const float4*)&A[(size_t)(m0 + r0) * K + c4];
    ra1 = *(const float4*)&A[(size_t)(m0 + r0 + 64) * K + c4];
    {
        int nb0 = n0 + r0, nb1 = n0 + r0 + 64;
        rb0 = (nb0 < N) ? *(const float4*)&B[(size_t)nb0 * K + c4] : make_float4(0, 0, 0, 0);
        rb1 = (nb1 < N) ? *(const float4*)&B[(size_t)nb1 * K + c4] : make_float4(0, 0, 0, 0);
    }
    As[c4 + 0][r0] = ra0.x; As[c4 + 1][r0] = ra0.y; As[c4 + 2][r0] = ra0.z; As[c4 + 3][r0] = ra0.w;
    As[c4 + 0][r0 + 64] = ra1.x; As[c4 + 1][r0 + 64] = ra1.y; As[c4 + 2][r0 + 64] = ra1.z; As[c4 + 3][r0 + 64] = ra1.w;
    Bs[c4 + 0][r0] = rb0.x; Bs[c4 + 1][r0] = rb0.y; Bs[c4 + 2][r0] = rb0.z; Bs[c4 + 3][r0] = rb0.w;
    Bs[c4 + 0][r0 + 64] = rb1.x; Bs[c4 + 1][r0 + 64] = rb1.y; Bs[c4 + 2][r0 + 64] = rb1.z; Bs[c4 + 3][r0 + 64] = rb1.w;
    __syncthreads();

    for (int kt = 0; kt < NKT; kt++) {
        const int kn = (kt + 1) * BK;
        if (kt + 1 < NKT) {
            ra0 = *(const float4*)&A[(size_t)(m0 + r0) * K + kn + c4];
            ra1 = *(const float4*)&A[(size_t)(m0 + r0 + 64) * K + kn + c4];
            int nb0 = n0 + r0, nb1 = n0 + r0 + 64;
            rb0 = (nb0 < N) ? *(const float4*)&B[(size_t)nb0 * K + kn + c4] : make_float4(0, 0, 0, 0);
            rb1 = (nb1 < N) ? *(const float4*)&B[(size_t)nb1 * K + kn + c4] : make_float4(0, 0, 0, 0);
        }
#pragma unroll
        for (int k = 0; k < BK; k++) {
            float a[8], b[8];
            *(float4*)&a[0] = *(const float4*)&As[k][tm];
            *(float4*)&a[4] = *(const float4*)&As[k][tm + 4];
            *(float4*)&b[0] = *(const float4*)&Bs[k][tn];
            *(float4*)&b[4] = *(const float4*)&Bs[k][tn + 4];
#pragma unroll
            for (int i = 0; i < 8; i++)
#pragma unroll
                for (int j = 0; j < 8; j++)
                    acc[i][j] = fmaf(a[i], b[j], acc[i][j]);
        }
        __syncthreads();
        if (kt + 1 < NKT) {
            As[c4 + 0][r0] = ra0.x; As[c4 + 1][r0] = ra0.y; As[c4 + 2][r0] = ra0.z; As[c4 + 3][r0] = ra0.w;
            As[c4 + 0][r0 + 64] = ra1.x; As[c4 + 1][r0 + 64] = ra1.y; As[c4 + 2][r0 + 64] = ra1.z; As[c4 + 3][r0 + 64] = ra1.w;
            Bs[c4 + 0][r0] = rb0.x; Bs[c4 + 1][r0] = rb0.y; Bs[c4 + 2][r0] = rb0.z; Bs[c4 + 3][r0] = rb0.w;
            Bs[c4 + 0][r0 + 64] = rb1.x; Bs[c4 + 1][r0 + 64] = rb1.y; Bs[c4 + 2][r0 + 64] = rb1.z; Bs[c4 + 3][r0 + 64] = rb1.w;
            __syncthreads();
        }
    }

    // epilogue: bias + activation + store
#pragma unroll
    for (int i = 0; i < 8; i++) {
        const int m = m0 + tm + i;
#pragma unroll
        for (int j = 0; j < 8; j++) {
            const int n = n0 + tn + j;
            if (n < N) {
                float v = acc[i][j] + bias[n];
                if (ACT == 1) v = gelu_exact(v);
                else if (ACT == 2) v = softplus_f(v);
                C[(size_t)m * N + n] = v;
            }
        }
    }
}

// ---------------------------------------------------------------------------
// Row LayerNorm over E=1024. One block (256 threads) per row; 1 float4/thread.
// ---------------------------------------------------------------------------
__global__ __launch_bounds__(256)
void ln_kernel(const float* __restrict__ X, float* __restrict__ Y,
               const float* __restrict__ gamma, const float* __restrict__ beta) {
    const int row = blockIdx.x;
    const int tid = threadIdx.x;
    const float4* x = (const float4*)(X + (size_t)row * En);
    float4* y = (float4*)(Y + (size_t)row * En);

    float4 v = x[tid];
    float s = v.x + v.y + v.z + v.w;
    float s2 = v.x * v.x + v.y * v.y + v.z * v.z + v.w * v.w;
#pragma unroll
    for (int o = 16; o; o >>= 1) {
        s += __shfl_xor_sync(0xffffffffu, s, o);
        s2 += __shfl_xor_sync(0xffffffffu, s2, o);
    }
    __shared__ float rs[8], rs2[8];
    __shared__ float smu, sinv;
    const int w = tid >> 5, l = tid & 31;
    if (l == 0) { rs[w] = s; rs2[w] = s2; }
    __syncthreads();
    if (tid == 0) {
        float a = 0.f, b = 0.f;
#pragma unroll
        for (int i = 0; i < 8; i++) { a += rs[i]; b += rs2[i]; }
        float mu = a * (1.0f / En);
        float var = b * (1.0f / En) - mu * mu;
        smu = mu;
        sinv = rsqrtf(var + 1e-5f);
    }
    __syncthreads();
    const float mu = smu, inv = sinv;
    float4 g4 = ((const float4*)gamma)[tid];
    float4 b4 = ((const float4*)beta)[tid];
    float4 o4;
    o4.x = (v.x - mu) * inv * g4.x + b4.x;
    o4.y = (v.y - mu) * inv * g4.y + b4.y;
    o4.z = (v.z - mu) * inv * g4.z + b4.z;
    o4.w = (v.w - mu) * inv * g4.w + b4.w;
    y[tid] = o4;
}

// ---------------------------------------------------------------------------
// Fused logits GEMM (64 tokens x 64 outputs, K=1024) + softmax -> pi
// ---------------------------------------------------------------------------
__global__ __launch_bounds__(256)
void pi_softmax_kernel(const float* __restrict__ H, const float* __restrict__ Wt,
                       const float* __restrict__ bt, float* __restrict__ pi_out) {
    constexpr int TM = 64, TK = 32, PAD = 4;
    __shared__ float hs[TK][TM + PAD];
    __shared__ float ws[TK][TM + PAD];
    __shared__ float ls[64][65];

    const int t0 = blockIdx.x * TM;
    const int tid = threadIdx.x;
    const int tx = tid & 15, ty = tid >> 4;
    const int r0 = tid >> 3;        // 0..31 (second load: +32)
    const int c4 = (tid & 7) * 4;   // 0..28

    float acc[4][4];
#pragma unroll
    for (int i = 0; i < 4; i++)
#pragma unroll
        for (int j = 0; j < 4; j++) acc[i][j] = 0.0f;

    for (int kt = 0; kt < En / TK; kt++) {
        const int kb = kt * TK;
        float4 h0 = *(const float4*)&H[(size_t)(t0 + r0) * En + kb + c4];
        float4 h1 = *(const float4*)&H[(size_t)(t0 + r0 + 32) * En + kb + c4];
        float4 w0 = *(const float4*)&Wt[(size_t)r0 * En + kb + c4];
        float4 w1 = *(const float4*)&Wt[(size_t)(r0 + 32) * En + kb + c4];
        __syncthreads();
        hs[c4 + 0][r0] = h0.x; hs[c4 + 1][r0] = h0.y; hs[c4 + 2][r0] = h0.z; hs[c4 + 3][r0] = h0.w;
        hs[c4 + 0][r0 + 32] = h1.x; hs[c4 + 1][r0 + 32] = h1.y; hs[c4 + 2][r0 + 32] = h1.z; hs[c4 + 3][r0 + 32] = h1.w;
        ws[c4 + 0][r0] = w0.x; ws[c4 + 1][r0] = w0.y; ws[c4 + 2][r0] = w0.z; ws[c4 + 3][r0] = w0.w;
        ws[c4 + 0][r0 + 32] = w1.x; ws[c4 + 1][r0 + 32] = w1.y; ws[c4 + 2][r0 + 32] = w1.z; ws[c4 + 3][r0 + 32] = w1.w;
        __syncthreads();
#pragma unroll
        for (int k = 0; k < TK; k++) {
            float a[4], b[4];
            *(float4*)a = *(const float4*)&hs[k][ty * 4];
            *(float4*)b = *(const float4*)&ws[k][tx * 4];
#pragma unroll
            for (int i = 0; i < 4; i++)
#pragma unroll
                for (int j = 0; j < 4; j++)
                    acc[i][j] = fmaf(a[i], b[j], acc[i][j]);
        }
    }
    __syncthreads();
#pragma unroll
    for (int i = 0; i < 4; i++)
#pragma unroll
        for (int j = 0; j < 4; j++)
            ls[ty * 4 + i][tx * 4 + j] = acc[i][j] + bt[tx * 4 + j];
    __syncthreads();

    const int w = tid >> 5, l = tid & 31;
    for (int t = w; t < 64; t += 8) {
        float v0 = ls[t][l], v1 = ls[t][l + 32];
        float mx = fmaxf(v0, v1);
#pragma unroll
        for (int o = 16; o; o >>= 1) mx = fmaxf(mx, __shfl_xor_sync(0xffffffffu, mx, o));
        float e0 = expf(v0 - mx), e1 = expf(v1 - mx);
        float sm = e0 + e1;
#pragma unroll
        for (int o = 16; o; o >>= 1) sm += __shfl_xor_sync(0xffffffffu, sm, o);
        float inv = 1.0f / sm;
        pi_out[(size_t)(t0 + t) * Vn + l] = e0 * inv;
        pi_out[(size_t)(t0 + t) * Vn + l + 32] = e1 * inv;
    }
}

// ---------------------------------------------------------------------------
// Per-token Q assembly: one block per token.
// Q[i][j] = Theta[k(i,j)] * sqrt(pi_j)/sqrt(pi_i) (i!=j), Q[i][i] = -rowsum.
// ---------------------------------------------------------------------------
__global__ __launch_bounds__(256)
void q_kernel(const float* __restrict__ theta, const float* __restrict__ pi,
              float* __restrict__ qout) {
    const int t = blockIdx.x;
    const int tid = threadIdx.x;
    __shared__ float th[NTn];
    __shared__ float sp[Vn], rp[Vn];
    __shared__ float qs[Vn][Vn + 1];
    __shared__ float rsum[Vn][4];

    const float4* trow = (const float4*)(theta + (size_t)t * NTn);
    for (int i = tid; i < NTn / 4; i += 256) ((float4*)th)[i] = trow[i];
    if (tid < Vn) {
        float p = pi[(size_t)t * Vn + tid];
        float s = sqrtf(p);
        sp[tid] = s;
        rp[tid] = 1.0f / s;
    }
    __syncthreads();

    const int i = tid >> 2, c = tid & 3;
    const float ri = rp[i];
    float part = 0.0f;
#pragma unroll
    for (int jj = 0; jj < 16; jj++) {
        const int j = c + jj * 4;
        float q = 0.0f;
        if (j != i) {
            const int a = min(i, j), b = max(i, j);
            const int k = a * 63 - (a * (a - 1)) / 2 + (b - a - 1);
            q = th[k] * sp[j] * ri;
        }
        qs[i][j] = q;
        part += q;
    }
    rsum[i][c] = part;
    __syncthreads();
    if (c == 0) {
        qs[i][i] = -(rsum[i][0] + rsum[i][1] + rsum[i][2] + rsum[i][3]);
    }
    __syncthreads();

    float* o = qout + (size_t)t * Vn * Vn;
#pragma unroll
    for (int r = 0; r < 4; r++) {
        const int e4 = tid + r * 256;
        const int e = e4 * 4;
        const int ii = e >> 6, j = e & 63;
        float4 v = make_float4(qs[ii][j], qs[ii][j + 1], qs[ii][j + 2], qs[ii][j + 3]);
        ((float4*)o)[e4] = v;
    }
}

// ---------------------------------------------------------------------------
extern "C" void kernel_launch(void* const* d_in, const int* in_sizes, int n_in,
                              void* d_out, int out_size) {
    const float* hx = (const float*)d_in[0];
    const float* Wd = (const float*)d_in[1];
    const float* bd = (const float*)d_in[2];
    const float* lng = (const float*)d_in[3];
    const float* lnb = (const float*)d_in[4];
    const float* Wt = (const float*)d_in[5];
    const float* bt = (const float*)d_in[6];
    const float* WT = (const float*)d_in[7];
    const float* bT = (const float*)d_in[8];

    float* out = (float*)d_out;
    float* qout = out;                                  // (B,L,V,V)
    float* piout = out + (size_t)Mn * Vn * Vn;          // (B,L,V)

    void* p;
    cudaGetSymbolAddress(&p, g_act);    float* gact = (float*)p;
    cudaGetSymbolAddress(&p, g_hidden); float* gh = (float*)p;
    cudaGetSymbolAddress(&p, g_theta);  float* gth = (float*)p;

    dim3 blk(256);

    // 1) dense + gelu
    dim3 grid1(En / 128, Mn / 128);  // (8, 64)
    gemm_nt_kernel<1><<<grid1, blk>>>(hx, Wd, bd, gact, Mn, En, En);

    // 2) LayerNorm
    ln_kernel<<<Mn, blk>>>(gact, gh, lng, lnb);

    // 3) logits + softmax -> pi (written directly into output)
    pi_softmax_kernel<<<Mn / 64, blk>>>(gh, Wt, bt, piout);

    // 4) Theta projection + softplus
    dim3 grid3((NTn + 127) / 128, Mn / 128);  // (16, 64)
    gemm_nt_kernel<2><<<grid3, blk>>>(gh, WT, bT, gth, Mn, NTn, En);

    // 5) Q assembly
    q_kernel<<<Mn, blk>>>(gth, piout, qout);
}

// round 6
// speedup vs baseline: 1.7036x; 1.7036x over previous
#include <cuda_runtime.h>
#include <cuda_bf16.h>
#include <math.h>
#include <stdint.h>

// ---------------------------------------------------------------------------
// Problem constants
// ---------------------------------------------------------------------------
namespace {
constexpr int Bn = 4, Ln = 2048, En = 1024, Vn = 64, NTn = 2016;
constexpr int Mn = Bn * Ln;          // 8192 tokens
constexpr int NTp = 2048;            // padded Theta output dim
}

// ---------------------------------------------------------------------------
// Scratch (static device globals — no runtime allocation)
// ---------------------------------------------------------------------------
__device__ __nv_bfloat16 g_hx_hi[(size_t)Mn * En];
__device__ __nv_bfloat16 g_hx_lo[(size_t)Mn * En];
__device__ __nv_bfloat16 g_Wd_hi[(size_t)En * En];
__device__ __nv_bfloat16 g_Wd_lo[(size_t)En * En];
__device__ __nv_bfloat16 g_WT_hi[(size_t)NTp * En];   // padded, rows >=2016 zero
__device__ __nv_bfloat16 g_WT_lo[(size_t)NTp * En];
__device__ __nv_bfloat16 g_H_hi[(size_t)Mn * En];
__device__ __nv_bfloat16 g_H_lo[(size_t)Mn * En];
__device__ float g_act[(size_t)Mn * En];      // gelu(dense) output f32
__device__ float g_hidden[(size_t)Mn * En];   // LayerNorm output f32
__device__ float g_theta[(size_t)Mn * NTp];   // softplus(Theta), padded stride

__device__ __forceinline__ float gelu_exact(float x) {
    return 0.5f * x * (1.0f + erff(x * 0.7071067811865476f));
}
__device__ __forceinline__ float softplus_f(float x) {
    if (x > 20.0f) return x;
    return log1pf(expf(x));
}

__device__ __forceinline__ uint32_t smem_to_u32(const void* p) {
    uint32_t a;
    asm("{ .reg .u64 t; cvta.to.shared.u64 t, %1; cvt.u32.u64 %0, t; }"
        : "=r"(a) : "l"(p));
    return a;
}

// ---------------------------------------------------------------------------
// mma.sync / ldmatrix / cp.async primitives (plain sm_80+ PTX, no 'a' features)
// ---------------------------------------------------------------------------
__device__ __forceinline__ void mma16816(float c[4], const uint32_t a[4],
                                         uint32_t b0, uint32_t b1) {
    asm volatile(
        "mma.sync.aligned.m16n8k16.row.col.f32.bf16.bf16.f32 "
        "{%0,%1,%2,%3}, {%4,%5,%6,%7}, {%8,%9}, {%0,%1,%2,%3};"
        : "+f"(c[0]), "+f"(c[1]), "+f"(c[2]), "+f"(c[3])
        : "r"(a[0]), "r"(a[1]), "r"(a[2]), "r"(a[3]), "r"(b0), "r"(b1));
}

__device__ __forceinline__ void ldm_x4(uint32_t r[4], uint32_t addr) {
    asm volatile("ldmatrix.sync.aligned.m8n8.x4.shared.b16 {%0,%1,%2,%3}, [%4];"
        : "=r"(r[0]), "=r"(r[1]), "=r"(r[2]), "=r"(r[3]) : "r"(addr));
}

__device__ __forceinline__ void cp16(uint32_t s, const void* g) {
    asm volatile("cp.async.cg.shared.global [%0], [%1], 16;" :: "r"(s), "l"(g));
}
#define CP_COMMIT() asm volatile("cp.async.commit_group;" ::: "memory")
#define CP_WAIT1()  asm volatile("cp.async.wait_group 1;" ::: "memory")
#define CP_WAIT0()  asm volatile("cp.async.wait_group 0;" ::: "memory")

// ---------------------------------------------------------------------------
// Split conversion: f32 -> bf16 hi + bf16 lo
// ---------------------------------------------------------------------------
__device__ __forceinline__ void split1(float v, __nv_bfloat16& h, __nv_bfloat16& l) {
    h = __float2bfloat16(v);
    l = __float2bfloat16(v - __bfloat162float(h));
}

__global__ __launch_bounds__(256)
void cvt_split_kernel(const float* __restrict__ src, __nv_bfloat16* __restrict__ hi,
                      __nv_bfloat16* __restrict__ lo, int n4) {
    for (int i = blockIdx.x * 256 + threadIdx.x; i < n4; i += gridDim.x * 256) {
        float4 v = ((const float4*)src)[i];
        __nv_bfloat16 h[4], l[4];
        split1(v.x, h[0], l[0]); split1(v.y, h[1], l[1]);
        split1(v.z, h[2], l[2]); split1(v.w, h[3], l[3]);
        ((uint2*)hi)[i] = *(uint2*)h;
        ((uint2*)lo)[i] = *(uint2*)l;
    }
}

// padded variant: rows >= rows_real are zero (cols multiple of 4)
__global__ __launch_bounds__(256)
void cvt_split_pad_kernel(const float* __restrict__ src, __nv_bfloat16* __restrict__ hi,
                          __nv_bfloat16* __restrict__ lo, int rows_real, int rows_pad,
                          int cols) {
    int n4 = rows_pad * cols / 4;
    int c4 = cols / 4;
    for (int i = blockIdx.x * 256 + threadIdx.x; i < n4; i += gridDim.x * 256) {
        int row = i / c4;
        float4 v = make_float4(0.f, 0.f, 0.f, 0.f);
        if (row < rows_real) {
            int col4 = i - row * c4;
            v = ((const float4*)src)[(size_t)row * c4 + col4];
        }
        __nv_bfloat16 h[4], l[4];
        split1(v.x, h[0], l[0]); split1(v.y, h[1], l[1]);
        split1(v.z, h[2], l[2]); split1(v.w, h[3], l[3]);
        ((uint2*)hi)[i] = *(uint2*)h;
        ((uint2*)lo)[i] = *(uint2*)l;
    }
}

// ---------------------------------------------------------------------------
// Split-bf16 HMMA GEMM:  C[m,n] = act( sum_k A[m,k]*B[n,k] + bias[n] )
// A: M x 1024 (hi/lo bf16), B: Npad x 1024 (hi/lo bf16). CTA tile 128x128,
// BK=32, 3-stage cp.async pipeline. K fixed = 1024.
// ---------------------------------------------------------------------------
namespace gm {
constexpr int ROWB = 80;            // 32 bf16 (64B) + 16B pad -> conflict-free ldmatrix
constexpr int TILE = 128 * ROWB;    // 10240 B, one 128-row subtile
constexpr int STAGE = 4 * TILE;     // A_hi, A_lo, B_hi, B_lo
constexpr int NSTG = 3;
constexpr int SMEM_BYTES = NSTG * STAGE;  // 122880
constexpr int NKT = 32;             // 1024 / 32
}

template <int ACT>  // 1 gelu, 2 softplus
__global__ __launch_bounds__(256)
void gemm_mma_kernel(const __nv_bfloat16* __restrict__ Ah, const __nv_bfloat16* __restrict__ Al,
                     const __nv_bfloat16* __restrict__ Bh, const __nv_bfloat16* __restrict__ Bl,
                     const float* __restrict__ bias, float* __restrict__ C,
                     int Nreal, int strideN) {
    extern __shared__ char smem[];
    const uint32_t sb = smem_to_u32(smem);
    const int tid = threadIdx.x, wid = tid >> 5, lane = tid & 31;
    const int m0 = blockIdx.y * 128, n0 = blockIdx.x * 128;
    const int wm = (wid & 1) * 64, wn = (wid >> 1) * 32;

    const __nv_bfloat16* srcs[4] = {Ah, Al, Bh, Bl};

    // copy one BK=32 k-slab of all four 128-row subtiles into stage s
    auto copy_stage = [&](int kt, int s) {
        const int kb = kt * 32;
#pragma unroll
        for (int r = 0; r < 8; r++) {
            int idx = r * 256 + tid;          // 0..2047
            int sub = idx >> 9;               // 0..3
            int row = (idx >> 2) & 127;
            int ch = idx & 3;                 // 16B chunk within 64B row
            const __nv_bfloat16* g = srcs[sub] +
                (size_t)((sub < 2 ? m0 : n0) + row) * 1024 + kb + ch * 8;
            uint32_t sa = sb + s * gm::STAGE + sub * gm::TILE + row * gm::ROWB + ch * 16;
            cp16(sa, g);
        }
    };

    float acc[4][4][4];
#pragma unroll
    for (int mi = 0; mi < 4; mi++)
#pragma unroll
        for (int ni = 0; ni < 4; ni++)
#pragma unroll
            for (int e = 0; e < 4; e++) acc[mi][ni][e] = 0.0f;

    copy_stage(0, 0); CP_COMMIT();
    copy_stage(1, 1); CP_COMMIT();

    for (int kt = 0; kt < gm::NKT; kt++) {
        const int s = kt % gm::NSTG;
        CP_WAIT1();
        __syncthreads();                       // tile kt resident, prev compute done
        if (kt + 2 < gm::NKT) {
            copy_stage(kt + 2, (kt + 2) % gm::NSTG);
            CP_COMMIT();
        }

        const uint32_t Ahs = sb + s * gm::STAGE;
        const uint32_t Als = Ahs + gm::TILE;
        const uint32_t Bhs = Ahs + 2 * gm::TILE;
        const uint32_t Bls = Ahs + 3 * gm::TILE;

#pragma unroll
        for (int ks = 0; ks < 2; ks++) {       // two k16 slices
            uint32_t ah[4][4], al[4][4], bh[2][4], bl[2][4];
#pragma unroll
            for (int mi = 0; mi < 4; mi++) {
                uint32_t off = (uint32_t)(wm + mi * 16 + (lane & 15)) * gm::ROWB
                             + ks * 32 + (lane >> 4) * 16;
                ldm_x4(ah[mi], Ahs + off);
                ldm_x4(al[mi], Als + off);
            }
#pragma unroll
            for (int g = 0; g < 2; g++) {
                uint32_t off = (uint32_t)(wn + g * 16 + ((lane >> 3) & 1) * 8 + (lane & 7)) * gm::ROWB
                             + ks * 32 + (lane >> 4) * 16;
                ldm_x4(bh[g], Bhs + off);
                ldm_x4(bl[g], Bls + off);
            }
#pragma unroll
            for (int mi = 0; mi < 4; mi++)
#pragma unroll
                for (int ni = 0; ni < 4; ni++) {
                    const int g = ni >> 1, u = ni & 1;
                    mma16816(acc[mi][ni], ah[mi], bh[g][u], bh[g][u + 2]);  // hi*hi
                    mma16816(acc[mi][ni], ah[mi], bl[g][u], bl[g][u + 2]);  // hi*lo
                    mma16816(acc[mi][ni], al[mi], bh[g][u], bh[g][u + 2]);  // lo*hi
                }
        }
    }
    CP_WAIT0();

    // epilogue: bias + activation + float2 stores
    const int rr = lane >> 2, cc = (lane & 3) * 2;
#pragma unroll
    for (int mi = 0; mi < 4; mi++) {
        const int m = m0 + wm + mi * 16 + rr;
#pragma unroll
        for (int ni = 0; ni < 4; ni++) {
            const int n = n0 + wn + ni * 8 + cc;
            float b0v = (n < Nreal) ? bias[n] : 0.0f;
            float b1v = (n + 1 < Nreal) ? bias[n + 1] : 0.0f;
            float v0 = acc[mi][ni][0] + b0v;
            float v1 = acc[mi][ni][1] + b1v;
            float v2 = acc[mi][ni][2] + b0v;
            float v3 = acc[mi][ni][3] + b1v;
            if (ACT == 1) {
                v0 = gelu_exact(v0); v1 = gelu_exact(v1);
                v2 = gelu_exact(v2); v3 = gelu_exact(v3);
            } else {
                v0 = softplus_f(v0); v1 = softplus_f(v1);
                v2 = softplus_f(v2); v3 = softplus_f(v3);
            }
            float2 p0 = make_float2(v0, v1);
            float2 p1 = make_float2(v2, v3);
            *(float2*)&C[(size_t)m * strideN + n] = p0;
            *(float2*)&C[(size_t)(m + 8) * strideN + n] = p1;
        }
    }
}

// ---------------------------------------------------------------------------
// Row LayerNorm over E=1024, fused bf16 hi/lo split output.
// ---------------------------------------------------------------------------
__global__ __launch_bounds__(256)
void ln_split_kernel(const float* __restrict__ X, float* __restrict__ Y,
                     __nv_bfloat16* __restrict__ Yhi, __nv_bfloat16* __restrict__ Ylo,
                     const float* __restrict__ gamma, const float* __restrict__ beta) {
    const int row = blockIdx.x;
    const int tid = threadIdx.x;
    const float4* x = (const float4*)(X + (size_t)row * En);

    float4 v = x[tid];
    float s = v.x + v.y + v.z + v.w;
    float s2 = v.x * v.x + v.y * v.y + v.z * v.z + v.w * v.w;
#pragma unroll
    for (int o = 16; o; o >>= 1) {
        s += __shfl_xor_sync(0xffffffffu, s, o);
        s2 += __shfl_xor_sync(0xffffffffu, s2, o);
    }
    __shared__ float rs[8], rs2[8];
    __shared__ float smu, sinv;
    const int w = tid >> 5, l = tid & 31;
    if (l == 0) { rs[w] = s; rs2[w] = s2; }
    __syncthreads();
    if (tid == 0) {
        float a = 0.f, b = 0.f;
#pragma unroll
        for (int i = 0; i < 8; i++) { a += rs[i]; b += rs2[i]; }
        float mu = a * (1.0f / En);
        float var = b * (1.0f / En) - mu * mu;
        smu = mu;
        sinv = rsqrtf(var + 1e-5f);
    }
    __syncthreads();
    const float mu = smu, inv = sinv;
    float4 g4 = ((const float4*)gamma)[tid];
    float4 b4 = ((const float4*)beta)[tid];
    float4 o4;
    o4.x = (v.x - mu) * inv * g4.x + b4.x;
    o4.y = (v.y - mu) * inv * g4.y + b4.y;
    o4.z = (v.z - mu) * inv * g4.z + b4.z;
    o4.w = (v.w - mu) * inv * g4.w + b4.w;
    ((float4*)(Y + (size_t)row * En))[tid] = o4;

    __nv_bfloat16 h[4], lo[4];
    split1(o4.x, h[0], lo[0]); split1(o4.y, h[1], lo[1]);
    split1(o4.z, h[2], lo[2]); split1(o4.w, h[3], lo[3]);
    ((uint2*)(Yhi + (size_t)row * En))[tid] = *(uint2*)h;
    ((uint2*)(Ylo + (size_t)row * En))[tid] = *(uint2*)lo;
}

// ---------------------------------------------------------------------------
// Fused logits GEMM (64 tokens x 64 outputs, K=1024) + softmax -> pi
// ---------------------------------------------------------------------------
__global__ __launch_bounds__(256)
void pi_softmax_kernel(const float* __restrict__ H, const float* __restrict__ Wt,
                       const float* __restrict__ bt, float* __restrict__ pi_out) {
    constexpr int TM = 64, TK = 32, PAD = 4;
    __shared__ float hs[TK][TM + PAD];
    __shared__ float ws[TK][TM + PAD];
    __shared__ float ls[64][65];

    const int t0 = blockIdx.x * TM;
    const int tid = threadIdx.x;
    const int tx = tid & 15, ty = tid >> 4;
    const int r0 = tid >> 3;
    const int c4 = (tid & 7) * 4;

    float acc[4][4];
#pragma unroll
    for (int i = 0; i < 4; i++)
#pragma unroll
        for (int j = 0; j < 4; j++) acc[i][j] = 0.0f;

    for (int kt = 0; kt < En / TK; kt++) {
        const int kb = kt * TK;
        float4 h0 = *(const float4*)&H[(size_t)(t0 + r0) * En + kb + c4];
        float4 h1 = *(const float4*)&H[(size_t)(t0 + r0 + 32) * En + kb + c4];
        float4 w0 = *(const float4*)&Wt[(size_t)r0 * En + kb + c4];
        float4 w1 = *(const float4*)&Wt[(size_t)(r0 + 32) * En + kb + c4];
        __syncthreads();
        hs[c4 + 0][r0] = h0.x; hs[c4 + 1][r0] = h0.y; hs[c4 + 2][r0] = h0.z; hs[c4 + 3][r0] = h0.w;
        hs[c4 + 0][r0 + 32] = h1.x; hs[c4 + 1][r0 + 32] = h1.y; hs[c4 + 2][r0 + 32] = h1.z; hs[c4 + 3][r0 + 32] = h1.w;
        ws[c4 + 0][r0] = w0.x; ws[c4 + 1][r0] = w0.y; ws[c4 + 2][r0] = w0.z; ws[c4 + 3][r0] = w0.w;
        ws[c4 + 0][r0 + 32] = w1.x; ws[c4 + 1][r0 + 32] = w1.y; ws[c4 + 2][r0 + 32] = w1.z; ws[c4 + 3][r0 + 32] = w1.w;
        __syncthreads();
#pragma unroll
        for (int k = 0; k < TK; k++) {
            float a[4], b[4];
            *(float4*)a = *(const float4*)&hs[k][ty * 4];
            *(float4*)b = *(const float4*)&ws[k][tx * 4];
#pragma unroll
            for (int i = 0; i < 4; i++)
#pragma unroll
                for (int j = 0; j < 4; j++)
                    acc[i][j] = fmaf(a[i], b[j], acc[i][j]);
        }
    }
    __syncthreads();
#pragma unroll
    for (int i = 0; i < 4; i++)
#pragma unroll
        for (int j = 0; j < 4; j++)
            ls[ty * 4 + i][tx * 4 + j] = acc[i][j] + bt[tx * 4 + j];
    __syncthreads();

    const int w = tid >> 5, l = tid & 31;
    for (int t = w; t < 64; t += 8) {
        float v0 = ls[t][l], v1 = ls[t][l + 32];
        float mx = fmaxf(v0, v1);
#pragma unroll
        for (int o = 16; o; o >>= 1) mx = fmaxf(mx, __shfl_xor_sync(0xffffffffu, mx, o));
        float e0 = expf(v0 - mx), e1 = expf(v1 - mx);
        float sm = e0 + e1;
#pragma unroll
        for (int o = 16; o; o >>= 1) sm += __shfl_xor_sync(0xffffffffu, sm, o);
        float inv = 1.0f / sm;
        pi_out[(size_t)(t0 + t) * Vn + l] = e0 * inv;
        pi_out[(size_t)(t0 + t) * Vn + l + 32] = e1 * inv;
    }
}

// ---------------------------------------------------------------------------
// Per-token Q assembly (theta has padded row stride NTp)
// ---------------------------------------------------------------------------
__global__ __launch_bounds__(256)
void q_kernel(const float* __restrict__ theta, const float* __restrict__ pi,
              float* __restrict__ qout) {
    const int t = blockIdx.x;
    const int tid = threadIdx.x;
    __shared__ float th[NTn];
    __shared__ float sp[Vn], rp[Vn];
    __shared__ float qs[Vn][Vn + 1];
    __shared__ float rsum[Vn][4];

    const float4* trow = (const float4*)(theta + (size_t)t * NTp);
    for (int i = tid; i < NTn / 4; i += 256) ((float4*)th)[i] = trow[i];
    if (tid < Vn) {
        float p = pi[(size_t)t * Vn + tid];
        float s = sqrtf(p);
        sp[tid] = s;
        rp[tid] = 1.0f / s;
    }
    __syncthreads();

    const int i = tid >> 2, c = tid & 3;
    const float ri = rp[i];
    float part = 0.0f;
#pragma unroll
    for (int jj = 0; jj < 16; jj++) {
        const int j = c + jj * 4;
        float q = 0.0f;
        if (j != i) {
            const int a = min(i, j), b = max(i, j);
            const int k = a * 63 - (a * (a - 1)) / 2 + (b - a - 1);
            q = th[k] * sp[j] * ri;
        }
        qs[i][j] = q;
        part += q;
    }
    rsum[i][c] = part;
    __syncthreads();
    if (c == 0) {
        qs[i][i] = -(rsum[i][0] + rsum[i][1] + rsum[i][2] + rsum[i][3]);
    }
    __syncthreads();

    float* o = qout + (size_t)t * Vn * Vn;
#pragma unroll
    for (int r = 0; r < 4; r++) {
        const int e4 = tid + r * 256;
        const int e = e4 * 4;
        const int ii = e >> 6, j = e & 63;
        float4 v = make_float4(qs[ii][j], qs[ii][j + 1], qs[ii][j + 2], qs[ii][j + 3]);
        ((float4*)o)[e4] = v;
    }
}

// ---------------------------------------------------------------------------
extern "C" void kernel_launch(void* const* d_in, const int* in_sizes, int n_in,
                              void* d_out, int out_size) {
    const float* hx = (const float*)d_in[0];
    const float* Wd = (const float*)d_in[1];
    const float* bd = (const float*)d_in[2];
    const float* lng = (const float*)d_in[3];
    const float* lnb = (const float*)d_in[4];
    const float* Wt = (const float*)d_in[5];
    const float* bt = (const float*)d_in[6];
    const float* WT = (const float*)d_in[7];
    const float* bT = (const float*)d_in[8];

    float* out = (float*)d_out;
    float* qout = out;                                  // (B,L,V,V)
    float* piout = out + (size_t)Mn * Vn * Vn;          // (B,L,V)

    void* p;
    cudaGetSymbolAddress(&p, g_hx_hi);  __nv_bfloat16* hxh = (__nv_bfloat16*)p;
    cudaGetSymbolAddress(&p, g_hx_lo);  __nv_bfloat16* hxl = (__nv_bfloat16*)p;
    cudaGetSymbolAddress(&p, g_Wd_hi);  __nv_bfloat16* wdh = (__nv_bfloat16*)p;
    cudaGetSymbolAddress(&p, g_Wd_lo);  __nv_bfloat16* wdl = (__nv_bfloat16*)p;
    cudaGetSymbolAddress(&p, g_WT_hi);  __nv_bfloat16* wth = (__nv_bfloat16*)p;
    cudaGetSymbolAddress(&p, g_WT_lo);  __nv_bfloat16* wtl = (__nv_bfloat16*)p;
    cudaGetSymbolAddress(&p, g_H_hi);   __nv_bfloat16* hh = (__nv_bfloat16*)p;
    cudaGetSymbolAddress(&p, g_H_lo);   __nv_bfloat16* hl = (__nv_bfloat16*)p;
    cudaGetSymbolAddress(&p, g_act);    float* gact = (float*)p;
    cudaGetSymbolAddress(&p, g_hidden); float* gh = (float*)p;
    cudaGetSymbolAddress(&p, g_theta);  float* gth = (float*)p;

    static bool attr_done = false;
    cudaFuncSetAttribute(gemm_mma_kernel<1>, cudaFuncAttributeMaxDynamicSharedMemorySize,
                         gm::SMEM_BYTES);
    cudaFuncSetAttribute(gemm_mma_kernel<2>, cudaFuncAttributeMaxDynamicSharedMemorySize,
                         gm::SMEM_BYTES);
    (void)attr_done;

    dim3 blk(256);

    // 0) split conversions
    cvt_split_kernel<<<2048, blk>>>(hx, hxh, hxl, Mn * En / 4);
    cvt_split_kernel<<<1024, blk>>>(Wd, wdh, wdl, En * En / 4);
    cvt_split_pad_kernel<<<1024, blk>>>(WT, wth, wtl, NTn, NTp, En);

    // 1) dense + gelu  (M=8192, N=1024)
    {
        dim3 grid(En / 128, Mn / 128);  // (8, 64)
        gemm_mma_kernel<1><<<grid, blk, gm::SMEM_BYTES>>>(hxh, hxl, wdh, wdl, bd, gact,
                                                          En, En);
    }

    // 2) LayerNorm + split
    ln_split_kernel<<<Mn, blk>>>(gact, gh, hh, hl, lng, lnb);

    // 3) logits + softmax -> pi (written directly into output)
    pi_softmax_kernel<<<Mn / 64, blk>>>(gh, Wt, bt, piout);

    // 4) Theta projection + softplus (M=8192, Npad=2048)
    {
        dim3 grid(NTp / 128, Mn / 128);  // (16, 64)
        gemm_mma_kernel<2><<<grid, blk, gm::SMEM_BYTES>>>(hh, hl, wth, wtl, bT, gth,
                                                          NTn, NTp);
    }

    // 5) Q assembly
    q_kernel<<<Mn, blk>>>(gth, piout, qout);
}

// round 9
// speedup vs baseline: 1.9421x; 1.1400x over previous
#include <cuda_runtime.h>
#include <cuda_bf16.h>
#include <math.h>
#include <stdint.h>

// ---------------------------------------------------------------------------
// Problem constants
// ---------------------------------------------------------------------------
namespace {
constexpr int Bn = 4, Ln = 2048, En = 1024, Vn = 64, NTn = 2016;
constexpr int Mn = Bn * Ln;          // 8192 tokens
constexpr int NTp = 2048;            // padded Theta output dim
}

// ---------------------------------------------------------------------------
// Scratch (static device globals — no runtime allocation)
// ---------------------------------------------------------------------------
__device__ __nv_bfloat16 g_hx_hi[(size_t)Mn * En];
__device__ __nv_bfloat16 g_hx_lo[(size_t)Mn * En];
__device__ __nv_bfloat16 g_Wd_hi[(size_t)En * En];
__device__ __nv_bfloat16 g_Wd_lo[(size_t)En * En];
__device__ __nv_bfloat16 g_WT_hi[(size_t)NTp * En];   // padded, rows >=2016 zero
__device__ __nv_bfloat16 g_WT_lo[(size_t)NTp * En];
__device__ __nv_bfloat16 g_H_hi[(size_t)Mn * En];
__device__ __nv_bfloat16 g_H_lo[(size_t)Mn * En];
__device__ float g_act[(size_t)Mn * En];      // gelu(dense) output f32
__device__ float g_hidden[(size_t)Mn * En];   // LayerNorm output f32
__device__ float g_theta[(size_t)Mn * NTp];   // softplus(Theta), padded stride

__device__ __forceinline__ float gelu_exact(float x) {
    return 0.5f * x * (1.0f + erff(x * 0.7071067811865476f));
}
__device__ __forceinline__ float softplus_f(float x) {
    if (x > 20.0f) return x;
    return log1pf(expf(x));
}

__device__ __forceinline__ uint32_t smem_to_u32(const void* p) {
    uint32_t a;
    asm("{ .reg .u64 t; cvta.to.shared.u64 t, %1; cvt.u32.u64 %0, t; }"
        : "=r"(a) : "l"(p));
    return a;
}

// ---------------------------------------------------------------------------
// mma.sync / ldmatrix / cp.async primitives (plain sm_80+ PTX, no 'a' features)
// ---------------------------------------------------------------------------
__device__ __forceinline__ void mma16816(float c[4], const uint32_t a[4],
                                         uint32_t b0, uint32_t b1) {
    asm volatile(
        "mma.sync.aligned.m16n8k16.row.col.f32.bf16.bf16.f32 "
        "{%0,%1,%2,%3}, {%4,%5,%6,%7}, {%8,%9}, {%0,%1,%2,%3};"
        : "+f"(c[0]), "+f"(c[1]), "+f"(c[2]), "+f"(c[3])
        : "r"(a[0]), "r"(a[1]), "r"(a[2]), "r"(a[3]), "r"(b0), "r"(b1));
}

__device__ __forceinline__ void ldm_x4(uint32_t r[4], uint32_t addr) {
    asm volatile("ldmatrix.sync.aligned.m8n8.x4.shared.b16 {%0,%1,%2,%3}, [%4];"
        : "=r"(r[0]), "=r"(r[1]), "=r"(r[2]), "=r"(r[3]) : "r"(addr));
}

__device__ __forceinline__ void cp16(uint32_t s, const void* g) {
    asm volatile("cp.async.cg.shared.global [%0], [%1], 16;" :: "r"(s), "l"(g));
}
#define CP_COMMIT() asm volatile("cp.async.commit_group;" ::: "memory")
#define CP_WAIT1()  asm volatile("cp.async.wait_group 1;" ::: "memory")
#define CP_WAIT0()  asm volatile("cp.async.wait_group 0;" ::: "memory")

// ---------------------------------------------------------------------------
// Split conversion: f32 -> bf16 hi + bf16 lo
// ---------------------------------------------------------------------------
__device__ __forceinline__ void split1(float v, __nv_bfloat16& h, __nv_bfloat16& l) {
    h = __float2bfloat16(v);
    l = __float2bfloat16(v - __bfloat162float(h));
}

__global__ __launch_bounds__(256)
void cvt_split_kernel(const float* __restrict__ src, __nv_bfloat16* __restrict__ hi,
                      __nv_bfloat16* __restrict__ lo, int n4) {
    for (int i = blockIdx.x * 256 + threadIdx.x; i < n4; i += gridDim.x * 256) {
        float4 v = ((const float4*)src)[i];
        __nv_bfloat16 h[4], l[4];
        split1(v.x, h[0], l[0]); split1(v.y, h[1], l[1]);
        split1(v.z, h[2], l[2]); split1(v.w, h[3], l[3]);
        ((uint2*)hi)[i] = *(uint2*)h;
        ((uint2*)lo)[i] = *(uint2*)l;
    }
}

// padded variant: rows >= rows_real are zero (cols multiple of 4)
__global__ __launch_bounds__(256)
void cvt_split_pad_kernel(const float* __restrict__ src, __nv_bfloat16* __restrict__ hi,
                          __nv_bfloat16* __restrict__ lo, int rows_real, int rows_pad,
                          int cols) {
    int n4 = rows_pad * cols / 4;
    int c4 = cols / 4;
    for (int i = blockIdx.x * 256 + threadIdx.x; i < n4; i += gridDim.x * 256) {
        int row = i / c4;
        float4 v = make_float4(0.f, 0.f, 0.f, 0.f);
        if (row < rows_real) {
            int col4 = i - row * c4;
            v = ((const float4*)src)[(size_t)row * c4 + col4];
        }
        __nv_bfloat16 h[4], l[4];
        split1(v.x, h[0], l[0]); split1(v.y, h[1], l[1]);
        split1(v.z, h[2], l[2]); split1(v.w, h[3], l[3]);
        ((uint2*)hi)[i] = *(uint2*)h;
        ((uint2*)lo)[i] = *(uint2*)l;
    }
}

// ---------------------------------------------------------------------------
// Split-bf16 HMMA GEMM:  C[m,n] = act( sum_k A[m,k]*B[n,k] + bias[n] )
// A: M x 1024 (hi/lo bf16), B: Npad x 1024 (hi/lo bf16). CTA tile 128x128,
// BK=32, 2-stage cp.async pipeline, 2 CTAs/SM. K fixed = 1024.
// ---------------------------------------------------------------------------
namespace gm {
constexpr int ROWB = 80;            // 32 bf16 (64B) + 16B pad -> conflict-free ldmatrix
constexpr int TILE = 128 * ROWB;    // 10240 B, one 128-row subtile
constexpr int STAGE = 4 * TILE;     // A_hi, A_lo, B_hi, B_lo
constexpr int NSTG = 2;
constexpr int SMEM_BYTES = NSTG * STAGE;  // 81920
constexpr int NKT = 32;             // 1024 / 32
}

template <int ACT>  // 1 gelu, 2 softplus
__global__ __launch_bounds__(256, 2)
void gemm_mma_kernel(const __nv_bfloat16* __restrict__ Ah, const __nv_bfloat16* __restrict__ Al,
                     const __nv_bfloat16* __restrict__ Bh, const __nv_bfloat16* __restrict__ Bl,
                     const float* __restrict__ bias, float* __restrict__ C,
                     int Nreal, int strideN) {
    extern __shared__ char smem[];
    const uint32_t sb = smem_to_u32(smem);
    const int tid = threadIdx.x, wid = tid >> 5, lane = tid & 31;
    const int m0 = blockIdx.y * 128, n0 = blockIdx.x * 128;
    const int wm = (wid & 1) * 64, wn = (wid >> 1) * 32;

    const __nv_bfloat16* srcs[4] = {Ah, Al, Bh, Bl};

    // per-thread copy slots (hoisted out of the loop)
    uint32_t cp_sa[8];
    const __nv_bfloat16* cp_g[8];
    {
        const int kb0 = 0;
#pragma unroll
        for (int r = 0; r < 8; r++) {
            int idx = r * 256 + tid;          // 0..2047
            int sub = idx >> 9;               // 0..3
            int row = (idx >> 2) & 127;
            int ch = idx & 3;                 // 16B chunk within 64B row
            cp_g[r] = srcs[sub] + (size_t)((sub < 2 ? m0 : n0) + row) * 1024 + kb0 + ch * 8;
            cp_sa[r] = sb + sub * gm::TILE + row * gm::ROWB + ch * 16;
        }
    }
    auto copy_stage = [&](int kt, int s) {
        const int kb = kt * 32;
        const uint32_t so = s * gm::STAGE;
#pragma unroll
        for (int r = 0; r < 8; r++) cp16(cp_sa[r] + so, cp_g[r] + kb);
    };

    // per-warp ldmatrix base offsets (hoisted)
    const uint32_t a_off = (uint32_t)(wm + (lane & 15)) * gm::ROWB + (lane >> 4) * 16;
    const uint32_t b_off = (uint32_t)(wn + ((lane >> 3) & 1) * 8 + (lane & 7)) * gm::ROWB
                         + (lane >> 4) * 16;

    float acc[4][4][4];
#pragma unroll
    for (int mi = 0; mi < 4; mi++)
#pragma unroll
        for (int ni = 0; ni < 4; ni++)
#pragma unroll
            for (int e = 0; e < 4; e++) acc[mi][ni][e] = 0.0f;

    copy_stage(0, 0); CP_COMMIT();

    for (int kt = 0; kt < gm::NKT; kt++) {
        const int s = kt & 1;
        if (kt + 1 < gm::NKT) {
            copy_stage(kt + 1, s ^ 1);
            CP_COMMIT();
            CP_WAIT1();
        } else {
            CP_WAIT0();
        }
        __syncthreads();                       // tile kt resident, prev compute done

        const uint32_t Ahs = sb + s * gm::STAGE;
        const uint32_t Als = Ahs + gm::TILE;
        const uint32_t Bhs = Ahs + 2 * gm::TILE;
        const uint32_t Bls = Ahs + 3 * gm::TILE;

#pragma unroll
        for (int ks = 0; ks < 2; ks++) {       // two k16 slices
            uint32_t ah[4][4], al[4][4], bh[2][4], bl[2][4];
            const uint32_t kso = ks * 32;
#pragma unroll
            for (int mi = 0; mi < 4; mi++) {
                uint32_t off = a_off + (uint32_t)(mi * 16) * gm::ROWB + kso;
                ldm_x4(ah[mi], Ahs + off);
                ldm_x4(al[mi], Als + off);
            }
#pragma unroll
            for (int g = 0; g < 2; g++) {
                uint32_t off = b_off + (uint32_t)(g * 16) * gm::ROWB + kso;
                ldm_x4(bh[g], Bhs + off);
                ldm_x4(bl[g], Bls + off);
            }
#pragma unroll
            for (int mi = 0; mi < 4; mi++)
#pragma unroll
                for (int ni = 0; ni < 4; ni++) {
                    const int g = ni >> 1, u = ni & 1;
                    mma16816(acc[mi][ni], ah[mi], bh[g][u], bh[g][u + 2]);  // hi*hi
                    mma16816(acc[mi][ni], ah[mi], bl[g][u], bl[g][u + 2]);  // hi*lo
                    mma16816(acc[mi][ni], al[mi], bh[g][u], bh[g][u + 2]);  // lo*hi
                }
        }
        __syncthreads();                       // compute done before overwrite
    }

    // epilogue: bias + activation + float2 stores
    const int rr = lane >> 2, cc = (lane & 3) * 2;
#pragma unroll
    for (int mi = 0; mi < 4; mi++) {
        const int m = m0 + wm + mi * 16 + rr;
#pragma unroll
        for (int ni = 0; ni < 4; ni++) {
            const int n = n0 + wn + ni * 8 + cc;
            float b0v = (n < Nreal) ? bias[n] : 0.0f;
            float b1v = (n + 1 < Nreal) ? bias[n + 1] : 0.0f;
            float v0 = acc[mi][ni][0] + b0v;
            float v1 = acc[mi][ni][1] + b1v;
            float v2 = acc[mi][ni][2] + b0v;
            float v3 = acc[mi][ni][3] + b1v;
            if (ACT == 1) {
                v0 = gelu_exact(v0); v1 = gelu_exact(v1);
                v2 = gelu_exact(v2); v3 = gelu_exact(v3);
            } else {
                v0 = softplus_f(v0); v1 = softplus_f(v1);
                v2 = softplus_f(v2); v3 = softplus_f(v3);
            }
            float2 p0 = make_float2(v0, v1);
            float2 p1 = make_float2(v2, v3);
            *(float2*)&C[(size_t)m * strideN + n] = p0;
            *(float2*)&C[(size_t)(m + 8) * strideN + n] = p1;
        }
    }
}

// ---------------------------------------------------------------------------
// Row LayerNorm over E=1024, fused bf16 hi/lo split output.
// ---------------------------------------------------------------------------
__global__ __launch_bounds__(256)
void ln_split_kernel(const float* __restrict__ X, float* __restrict__ Y,
                     __nv_bfloat16* __restrict__ Yhi, __nv_bfloat16* __restrict__ Ylo,
                     const float* __restrict__ gamma, const float* __restrict__ beta) {
    const int row = blockIdx.x;
    const int tid = threadIdx.x;
    const float4* x = (const float4*)(X + (size_t)row * En);

    float4 v = x[tid];
    float s = v.x + v.y + v.z + v.w;
    float s2 = v.x * v.x + v.y * v.y + v.z * v.z + v.w * v.w;
#pragma unroll
    for (int o = 16; o; o >>= 1) {
        s += __shfl_xor_sync(0xffffffffu, s, o);
        s2 += __shfl_xor_sync(0xffffffffu, s2, o);
    }
    __shared__ float rs[8], rs2[8];
    __shared__ float smu, sinv;
    const int w = tid >> 5, l = tid & 31;
    if (l == 0) { rs[w] = s; rs2[w] = s2; }
    __syncthreads();
    if (tid == 0) {
        float a = 0.f, b = 0.f;
#pragma unroll
        for (int i = 0; i < 8; i++) { a += rs[i]; b += rs2[i]; }
        float mu = a * (1.0f / En);
        float var = b * (1.0f / En) - mu * mu;
        smu = mu;
        sinv = rsqrtf(var + 1e-5f);
    }
    __syncthreads();
    const float mu = smu, inv = sinv;
    float4 g4 = ((const float4*)gamma)[tid];
    float4 b4 = ((const float4*)beta)[tid];
    float4 o4;
    o4.x = (v.x - mu) * inv * g4.x + b4.x;
    o4.y = (v.y - mu) * inv * g4.y + b4.y;
    o4.z = (v.z - mu) * inv * g4.z + b4.z;
    o4.w = (v.w - mu) * inv * g4.w + b4.w;
    ((float4*)(Y + (size_t)row * En))[tid] = o4;

    __nv_bfloat16 h[4], lo[4];
    split1(o4.x, h[0], lo[0]); split1(o4.y, h[1], lo[1]);
    split1(o4.z, h[2], lo[2]); split1(o4.w, h[3], lo[3]);
    ((uint2*)(Yhi + (size_t)row * En))[tid] = *(uint2*)h;
    ((uint2*)(Ylo + (size_t)row * En))[tid] = *(uint2*)lo;
}

// ---------------------------------------------------------------------------
// Fused logits GEMM (64 tokens x 64 outputs, K=1024) + softmax -> pi
// ---------------------------------------------------------------------------
__global__ __launch_bounds__(256)
void pi_softmax_kernel(const float* __restrict__ H, const float* __restrict__ Wt,
                       const float* __restrict__ bt, float* __restrict__ pi_out) {
    constexpr int TM = 64, TK = 32, PAD = 4;
    __shared__ float hs[TK][TM + PAD];
    __shared__ float ws[TK][TM + PAD];
    __shared__ float ls[64][65];

    const int t0 = blockIdx.x * TM;
    const int tid = threadIdx.x;
    const int tx = tid & 15, ty = tid >> 4;
    const int r0 = tid >> 3;
    const int c4 = (tid & 7) * 4;

    float acc[4][4];
#pragma unroll
    for (int i = 0; i < 4; i++)
#pragma unroll
        for (int j = 0; j < 4; j++) acc[i][j] = 0.0f;

    for (int kt = 0; kt < En / TK; kt++) {
        const int kb = kt * TK;
        float4 h0 = *(const float4*)&H[(size_t)(t0 + r0) * En + kb + c4];
        float4 h1 = *(const float4*)&H[(size_t)(t0 + r0 + 32) * En + kb + c4];
        float4 w0 = *(const float4*)&Wt[(size_t)r0 * En + kb + c4];
        float4 w1 = *(const float4*)&Wt[(size_t)(r0 + 32) * En + kb + c4];
        __syncthreads();
        hs[c4 + 0][r0] = h0.x; hs[c4 + 1][r0] = h0.y; hs[c4 + 2][r0] = h0.z; hs[c4 + 3][r0] = h0.w;
        hs[c4 + 0][r0 + 32] = h1.x; hs[c4 + 1][r0 + 32] = h1.y; hs[c4 + 2][r0 + 32] = h1.z; hs[c4 + 3][r0 + 32] = h1.w;
        ws[c4 + 0][r0] = w0.x; ws[c4 + 1][r0] = w0.y; ws[c4 + 2][r0] = w0.z; ws[c4 + 3][r0] = w0.w;
        ws[c4 + 0][r0 + 32] = w1.x; ws[c4 + 1][r0 + 32] = w1.y; ws[c4 + 2][r0 + 32] = w1.z; ws[c4 + 3][r0 + 32] = w1.w;
        __syncthreads();
#pragma unroll
        for (int k = 0; k < TK; k++) {
            float a[4], b[4];
            *(float4*)a = *(const float4*)&hs[k][ty * 4];
            *(float4*)b = *(const float4*)&ws[k][tx * 4];
#pragma unroll
            for (int i = 0; i < 4; i++)
#pragma unroll
                for (int j = 0; j < 4; j++)
                    acc[i][j] = fmaf(a[i], b[j], acc[i][j]);
        }
    }
    __syncthreads();
#pragma unroll
    for (int i = 0; i < 4; i++)
#pragma unroll
        for (int j = 0; j < 4; j++)
            ls[ty * 4 + i][tx * 4 + j] = acc[i][j] + bt[tx * 4 + j];
    __syncthreads();

    const int w = tid >> 5, l = tid & 31;
    for (int t = w; t < 64; t += 8) {
        float v0 = ls[t][l], v1 = ls[t][l + 32];
        float mx = fmaxf(v0, v1);
#pragma unroll
        for (int o = 16; o; o >>= 1) mx = fmaxf(mx, __shfl_xor_sync(0xffffffffu, mx, o));
        float e0 = expf(v0 - mx), e1 = expf(v1 - mx);
        float sm = e0 + e1;
#pragma unroll
        for (int o = 16; o; o >>= 1) sm += __shfl_xor_sync(0xffffffffu, sm, o);
        float inv = 1.0f / sm;
        pi_out[(size_t)(t0 + t) * Vn + l] = e0 * inv;
        pi_out[(size_t)(t0 + t) * Vn + l + 32] = e1 * inv;
    }
}

// ---------------------------------------------------------------------------
// Per-token Q assembly (theta has padded row stride NTp)
// ---------------------------------------------------------------------------
__global__ __launch_bounds__(256)
void q_kernel(const float* __restrict__ theta, const float* __restrict__ pi,
              float* __restrict__ qout) {
    const int t = blockIdx.x;
    const int tid = threadIdx.x;
    __shared__ float th[NTn];
    __shared__ float sp[Vn], rp[Vn];
    __shared__ float qs[Vn][Vn + 1];
    __shared__ float rsum[Vn][4];

    const float4* trow = (const float4*)(theta + (size_t)t * NTp);
    for (int i = tid; i < NTn / 4; i += 256) ((float4*)th)[i] = trow[i];
    if (tid < Vn) {
        float p = pi[(size_t)t * Vn + tid];
        float s = sqrtf(p);
        sp[tid] = s;
        rp[tid] = 1.0f / s;
    }
    __syncthreads();

    const int i = tid >> 2, c = tid & 3;
    const float ri = rp[i];
    float part = 0.0f;
#pragma unroll
    for (int jj = 0; jj < 16; jj++) {
        const int j = c + jj * 4;
        float q = 0.0f;
        if (j != i) {
            const int a = min(i, j), b = max(i, j);
            const int k = a * 63 - (a * (a - 1)) / 2 + (b - a - 1);
            q = th[k] * sp[j] * ri;
        }
        qs[i][j] = q;
        part += q;
    }
    rsum[i][c] = part;
    __syncthreads();
    if (c == 0) {
        qs[i][i] = -(rsum[i][0] + rsum[i][1] + rsum[i][2] + rsum[i][3]);
    }
    __syncthreads();

    float* o = qout + (size_t)t * Vn * Vn;
#pragma unroll
    for (int r = 0; r < 4; r++) {
        const int e4 = tid + r * 256;
        const int e = e4 * 4;
        const int ii = e >> 6, j = e & 63;
        float4 v = make_float4(qs[ii][j], qs[ii][j + 1], qs[ii][j + 2], qs[ii][j + 3]);
        ((float4*)o)[e4] = v;
    }
}

// ---------------------------------------------------------------------------
extern "C" void kernel_launch(void* const* d_in, const int* in_sizes, int n_in,
                              void* d_out, int out_size) {
    const float* hx = (const float*)d_in[0];
    const float* Wd = (const float*)d_in[1];
    const float* bd = (const float*)d_in[2];
    const float* lng = (const float*)d_in[3];
    const float* lnb = (const float*)d_in[4];
    const float* Wt = (const float*)d_in[5];
    const float* bt = (const float*)d_in[6];
    const float* WT = (const float*)d_in[7];
    const float* bT = (const float*)d_in[8];

    float* out = (float*)d_out;
    float* qout = out;                                  // (B,L,V,V)
    float* piout = out + (size_t)Mn * Vn * Vn;          // (B,L,V)

    void* p;
    cudaGetSymbolAddress(&p, g_hx_hi);  __nv_bfloat16* hxh = (__nv_bfloat16*)p;
    cudaGetSymbolAddress(&p, g_hx_lo);  __nv_bfloat16* hxl = (__nv_bfloat16*)p;
    cudaGetSymbolAddress(&p, g_Wd_hi);  __nv_bfloat16* wdh = (__nv_bfloat16*)p;
    cudaGetSymbolAddress(&p, g_Wd_lo);  __nv_bfloat16* wdl = (__nv_bfloat16*)p;
    cudaGetSymbolAddress(&p, g_WT_hi);  __nv_bfloat16* wth = (__nv_bfloat16*)p;
    cudaGetSymbolAddress(&p, g_WT_lo);  __nv_bfloat16* wtl = (__nv_bfloat16*)p;
    cudaGetSymbolAddress(&p, g_H_hi);   __nv_bfloat16* hh = (__nv_bfloat16*)p;
    cudaGetSymbolAddress(&p, g_H_lo);   __nv_bfloat16* hl = (__nv_bfloat16*)p;
    cudaGetSymbolAddress(&p, g_act);    float* gact = (float*)p;
    cudaGetSymbolAddress(&p, g_hidden); float* gh = (float*)p;
    cudaGetSymbolAddress(&p, g_theta);  float* gth = (float*)p;

    cudaFuncSetAttribute(gemm_mma_kernel<1>, cudaFuncAttributeMaxDynamicSharedMemorySize,
                         gm::SMEM_BYTES);
    cudaFuncSetAttribute(gemm_mma_kernel<2>, cudaFuncAttributeMaxDynamicSharedMemorySize,
                         gm::SMEM_BYTES);

    dim3 blk(256);

    // 0) split conversions
    cvt_split_kernel<<<2048, blk>>>(hx, hxh, hxl, Mn * En / 4);
    cvt_split_kernel<<<1024, blk>>>(Wd, wdh, wdl, En * En / 4);
    cvt_split_pad_kernel<<<1024, blk>>>(WT, wth, wtl, NTn, NTp, En);

    // 1) dense + gelu  (M=8192, N=1024)
    {
        dim3 grid(En / 128, Mn / 128);  // (8, 64)
        gemm_mma_kernel<1><<<grid, blk, gm::SMEM_BYTES>>>(hxh, hxl, wdh, wdl, bd, gact,
                                                          En, En);
    }

    // 2) LayerNorm + split
    ln_split_kernel<<<Mn, blk>>>(gact, gh, hh, hl, lng, lnb);

    // 3) logits + softmax -> pi (written directly into output)
    pi_softmax_kernel<<<Mn / 64, blk>>>(gh, Wt, bt, piout);

    // 4) Theta projection + softplus (M=8192, Npad=2048)
    {
        dim3 grid(NTp / 128, Mn / 128);  // (16, 64)
        gemm_mma_kernel<2><<<grid, blk, gm::SMEM_BYTES>>>(hh, hl, wth, wtl, bT, gth,
                                                          NTn, NTp);
    }

    // 5) Q assembly
    q_kernel<<<Mn, blk>>>(gth, piout, qout);
}

// round 11
// speedup vs baseline: 2.1728x; 1.1188x over previous
#include <cuda_runtime.h>
#include <cuda_bf16.h>
#include <math.h>
#include <stdint.h>

// ---------------------------------------------------------------------------
// Problem constants
// ---------------------------------------------------------------------------
namespace {
constexpr int Bn = 4, Ln = 2048, En = 1024, Vn = 64, NTn = 2016;
constexpr int Mn = Bn * Ln;          // 8192 tokens
constexpr int NTp = 2048;            // padded Theta output dim
}

// ---------------------------------------------------------------------------
// Scratch (static device globals — no runtime allocation)
// ---------------------------------------------------------------------------
__device__ __nv_bfloat16 g_hx_hi[(size_t)Mn * En];
__device__ __nv_bfloat16 g_hx_lo[(size_t)Mn * En];
__device__ __nv_bfloat16 g_Wd_hi[(size_t)En * En];
__device__ __nv_bfloat16 g_Wd_lo[(size_t)En * En];
__device__ __nv_bfloat16 g_WT_hi[(size_t)NTp * En];   // padded, rows >=2016 zero
__device__ __nv_bfloat16 g_WT_lo[(size_t)NTp * En];
__device__ __nv_bfloat16 g_H_hi[(size_t)Mn * En];
__device__ __nv_bfloat16 g_H_lo[(size_t)Mn * En];
__device__ float g_act[(size_t)Mn * En];      // gelu(dense) output f32
__device__ float g_hidden[(size_t)Mn * En];   // LayerNorm output f32
__device__ float g_theta[(size_t)Mn * NTp];   // softplus(Theta), padded stride

__device__ __forceinline__ float gelu_exact(float x) {
    return 0.5f * x * (1.0f + erff(x * 0.7071067811865476f));
}
__device__ __forceinline__ float softplus_f(float x) {
    if (x > 20.0f) return x;
    return log1pf(expf(x));
}

__device__ __forceinline__ uint32_t smem_to_u32(const void* p) {
    uint32_t a;
    asm("{ .reg .u64 t; cvta.to.shared.u64 t, %1; cvt.u32.u64 %0, t; }"
        : "=r"(a) : "l"(p));
    return a;
}

// ---------------------------------------------------------------------------
// mma.sync / ldmatrix / cp.async primitives (plain sm_80+ PTX, no 'a' features)
// ---------------------------------------------------------------------------
__device__ __forceinline__ void mma16816(float c[4], const uint32_t a[4],
                                         uint32_t b0, uint32_t b1) {
    asm volatile(
        "mma.sync.aligned.m16n8k16.row.col.f32.bf16.bf16.f32 "
        "{%0,%1,%2,%3}, {%4,%5,%6,%7}, {%8,%9}, {%0,%1,%2,%3};"
        : "+f"(c[0]), "+f"(c[1]), "+f"(c[2]), "+f"(c[3])
        : "r"(a[0]), "r"(a[1]), "r"(a[2]), "r"(a[3]), "r"(b0), "r"(b1));
}

__device__ __forceinline__ void ldm_x4(uint32_t r[4], uint32_t addr) {
    asm volatile("ldmatrix.sync.aligned.m8n8.x4.shared.b16 {%0,%1,%2,%3}, [%4];"
        : "=r"(r[0]), "=r"(r[1]), "=r"(r[2]), "=r"(r[3]) : "r"(addr));
}

__device__ __forceinline__ void cp16(uint32_t s, const void* g) {
    asm volatile("cp.async.cg.shared.global [%0], [%1], 16;" :: "r"(s), "l"(g));
}
#define CP_COMMIT() asm volatile("cp.async.commit_group;" ::: "memory")
#define CP_WAIT1()  asm volatile("cp.async.wait_group 1;" ::: "memory")
#define CP_WAIT0()  asm volatile("cp.async.wait_group 0;" ::: "memory")

// ---------------------------------------------------------------------------
// Split conversion: f32 -> bf16 hi + bf16 lo
// ---------------------------------------------------------------------------
__device__ __forceinline__ void split1(float v, __nv_bfloat16& h, __nv_bfloat16& l) {
    h = __float2bfloat16(v);
    l = __float2bfloat16(v - __bfloat162float(h));
}

__global__ __launch_bounds__(256)
void cvt_split_kernel(const float* __restrict__ src, __nv_bfloat16* __restrict__ hi,
                      __nv_bfloat16* __restrict__ lo, int n4) {
    for (int i = blockIdx.x * 256 + threadIdx.x; i < n4; i += gridDim.x * 256) {
        float4 v = ((const float4*)src)[i];
        __nv_bfloat16 h[4], l[4];
        split1(v.x, h[0], l[0]); split1(v.y, h[1], l[1]);
        split1(v.z, h[2], l[2]); split1(v.w, h[3], l[3]);
        ((uint2*)hi)[i] = *(uint2*)h;
        ((uint2*)lo)[i] = *(uint2*)l;
    }
}

// padded variant: rows >= rows_real are zero (cols multiple of 4)
__global__ __launch_bounds__(256)
void cvt_split_pad_kernel(const float* __restrict__ src, __nv_bfloat16* __restrict__ hi,
                          __nv_bfloat16* __restrict__ lo, int rows_real, int rows_pad,
                          int cols) {
    int n4 = rows_pad * cols / 4;
    int c4 = cols / 4;
    for (int i = blockIdx.x * 256 + threadIdx.x; i < n4; i += gridDim.x * 256) {
        int row = i / c4;
        float4 v = make_float4(0.f, 0.f, 0.f, 0.f);
        if (row < rows_real) {
            int col4 = i - row * c4;
            v = ((const float4*)src)[(size_t)row * c4 + col4];
        }
        __nv_bfloat16 h[4], l[4];
        split1(v.x, h[0], l[0]); split1(v.y, h[1], l[1]);
        split1(v.z, h[2], l[2]); split1(v.w, h[3], l[3]);
        ((uint2*)hi)[i] = *(uint2*)h;
        ((uint2*)lo)[i] = *(uint2*)l;
    }
}

// ---------------------------------------------------------------------------
// Split-bf16 HMMA GEMM:  C[m,n] = act( sum_k A[m,k]*B[n,k] + bias[n] )
// A: M x 1024 (hi/lo bf16), B: Npad x 1024 (hi/lo bf16). CTA tile 128x128,
// BK=32, 3-stage cp.async pipeline (depth-2 prefetch), 2 CTAs/SM, swizzled
// 64B smem rows (conflict-free ldmatrix, no padding). K fixed = 1024.
// ---------------------------------------------------------------------------
namespace gm {
constexpr int ROWB = 64;            // 32 bf16, XOR-swizzled chunks
constexpr int TILE = 128 * ROWB;    // 8192 B, one 128-row subtile
constexpr int STAGE = 4 * TILE;     // A_hi, A_lo, B_hi, B_lo = 32768 B
constexpr int NSTG = 3;
constexpr int SMEM_BYTES = NSTG * STAGE;  // 98304
constexpr int NKT = 32;             // 1024 / 32
}

// swizzled byte offset within a 128x64B subtile
__device__ __forceinline__ uint32_t swz(uint32_t row, uint32_t ch) {
    return row * 64u + ((ch ^ ((row >> 1) & 3u)) << 4);
}

template <int ACT>  // 1 gelu, 2 softplus
__global__ __launch_bounds__(256, 2)
void gemm_mma_kernel(const __nv_bfloat16* __restrict__ Ah, const __nv_bfloat16* __restrict__ Al,
                     const __nv_bfloat16* __restrict__ Bh, const __nv_bfloat16* __restrict__ Bl,
                     const float* __restrict__ bias, float* __restrict__ C,
                     int Nreal, int strideN) {
    extern __shared__ char smem[];
    const uint32_t sb = smem_to_u32(smem);
    const int tid = threadIdx.x, wid = tid >> 5, lane = tid & 31;
    const int m0 = blockIdx.y * 128, n0 = blockIdx.x * 128;
    const int wm = (wid & 1) * 64, wn = (wid >> 1) * 32;

    const __nv_bfloat16* srcs[4] = {Ah, Al, Bh, Bl};

    // per-thread copy slots (swizzled smem dst hoisted; gmem base hoisted)
    uint32_t cp_sa[8];
    const __nv_bfloat16* cp_g[8];
#pragma unroll
    for (int r = 0; r < 8; r++) {
        int idx = r * 256 + tid;          // 0..2047
        int sub = idx >> 9;               // 0..3
        uint32_t row = (idx >> 2) & 127;
        uint32_t ch = idx & 3;            // 16B chunk within 64B row
        cp_g[r] = srcs[sub] + (size_t)((sub < 2 ? m0 : n0) + row) * 1024 + ch * 8;
        cp_sa[r] = sb + sub * gm::TILE + swz(row, ch);
    }
    auto copy_stage = [&](int kt, int s) {
        const int kb = kt * 32;
        const uint32_t so = (uint32_t)s * gm::STAGE;
#pragma unroll
        for (int r = 0; r < 8; r++) cp16(cp_sa[r] + so, cp_g[r] + kb);
    };

    // per-warp ldmatrix addressing: row and swizzle-select per fragment group
    const uint32_t hi16 = (lane >> 4);         // 0/1: +16B column within k16 slice
    uint32_t a_off[2][4], b_off[2][2];
#pragma unroll
    for (int mi = 0; mi < 4; mi++) {
        uint32_t row = (uint32_t)(wm + mi * 16 + (lane & 15));
#pragma unroll
        for (int ks = 0; ks < 2; ks++)
            a_off[ks][mi] = swz(row, ks * 2 + hi16);
    }
#pragma unroll
    for (int g = 0; g < 2; g++) {
        uint32_t row = (uint32_t)(wn + g * 16 + ((lane >> 3) & 1) * 8 + (lane & 7));
#pragma unroll
        for (int ks = 0; ks < 2; ks++)
            b_off[ks][g] = swz(row, ks * 2 + hi16);
    }

    float acc[4][4][4];
#pragma unroll
    for (int mi = 0; mi < 4; mi++)
#pragma unroll
        for (int ni = 0; ni < 4; ni++)
#pragma unroll
            for (int e = 0; e < 4; e++) acc[mi][ni][e] = 0.0f;

    copy_stage(0, 0); CP_COMMIT();
    copy_stage(1, 1); CP_COMMIT();

    int scur = 0, scpy = 2;
    for (int kt = 0; kt < gm::NKT; kt++) {
        if (kt + 1 < gm::NKT) { CP_WAIT1(); } else { CP_WAIT0(); }
        __syncthreads();  // copy(kt) visible; compute(kt-1) done by all warps
        if (kt + 2 < gm::NKT) {
            copy_stage(kt + 2, scpy);
            CP_COMMIT();
            if (++scpy == gm::NSTG) scpy = 0;
        }

        const uint32_t Ahs = sb + (uint32_t)scur * gm::STAGE;
        const uint32_t Als = Ahs + gm::TILE;
        const uint32_t Bhs = Ahs + 2 * gm::TILE;
        const uint32_t Bls = Ahs + 3 * gm::TILE;
        if (++scur == gm::NSTG) scur = 0;

#pragma unroll
        for (int ks = 0; ks < 2; ks++) {       // two k16 slices
            uint32_t ah[4][4], al[4][4], bh[2][4], bl[2][4];
#pragma unroll
            for (int mi = 0; mi < 4; mi++) {
                ldm_x4(ah[mi], Ahs + a_off[ks][mi]);
                ldm_x4(al[mi], Als + a_off[ks][mi]);
            }
#pragma unroll
            for (int g = 0; g < 2; g++) {
                ldm_x4(bh[g], Bhs + b_off[ks][g]);
                ldm_x4(bl[g], Bls + b_off[ks][g]);
            }
#pragma unroll
            for (int mi = 0; mi < 4; mi++)
#pragma unroll
                for (int ni = 0; ni < 4; ni++) {
                    const int g = ni >> 1, u = ni & 1;
                    mma16816(acc[mi][ni], ah[mi], bh[g][u], bh[g][u + 2]);  // hi*hi
                    mma16816(acc[mi][ni], ah[mi], bl[g][u], bl[g][u + 2]);  // hi*lo
                    mma16816(acc[mi][ni], al[mi], bh[g][u], bh[g][u + 2]);  // lo*hi
                }
        }
    }

    // epilogue: bias + activation + float2 stores
    const int rr = lane >> 2, cc = (lane & 3) * 2;
#pragma unroll
    for (int mi = 0; mi < 4; mi++) {
        const int m = m0 + wm + mi * 16 + rr;
#pragma unroll
        for (int ni = 0; ni < 4; ni++) {
            const int n = n0 + wn + ni * 8 + cc;
            float b0v = (n < Nreal) ? bias[n] : 0.0f;
            float b1v = (n + 1 < Nreal) ? bias[n + 1] : 0.0f;
            float v0 = acc[mi][ni][0] + b0v;
            float v1 = acc[mi][ni][1] + b1v;
            float v2 = acc[mi][ni][2] + b0v;
            float v3 = acc[mi][ni][3] + b1v;
            if (ACT == 1) {
                v0 = gelu_exact(v0); v1 = gelu_exact(v1);
                v2 = gelu_exact(v2); v3 = gelu_exact(v3);
            } else {
                v0 = softplus_f(v0); v1 = softplus_f(v1);
                v2 = softplus_f(v2); v3 = softplus_f(v3);
            }
            float2 p0 = make_float2(v0, v1);
            float2 p1 = make_float2(v2, v3);
            *(float2*)&C[(size_t)m * strideN + n] = p0;
            *(float2*)&C[(size_t)(m + 8) * strideN + n] = p1;
        }
    }
}

// ---------------------------------------------------------------------------
// Row LayerNorm over E=1024, fused bf16 hi/lo split output.
// ---------------------------------------------------------------------------
__global__ __launch_bounds__(256)
void ln_split_kernel(const float* __restrict__ X, float* __restrict__ Y,
                     __nv_bfloat16* __restrict__ Yhi, __nv_bfloat16* __restrict__ Ylo,
                     const float* __restrict__ gamma, const float* __restrict__ beta) {
    const int row = blockIdx.x;
    const int tid = threadIdx.x;
    const float4* x = (const float4*)(X + (size_t)row * En);

    float4 v = x[tid];
    float s = v.x + v.y + v.z + v.w;
    float s2 = v.x * v.x + v.y * v.y + v.z * v.z + v.w * v.w;
#pragma unroll
    for (int o = 16; o; o >>= 1) {
        s += __shfl_xor_sync(0xffffffffu, s, o);
        s2 += __shfl_xor_sync(0xffffffffu, s2, o);
    }
    __shared__ float rs[8], rs2[8];
    __shared__ float smu, sinv;
    const int w = tid >> 5, l = tid & 31;
    if (l == 0) { rs[w] = s; rs2[w] = s2; }
    __syncthreads();
    if (tid == 0) {
        float a = 0.f, b = 0.f;
#pragma unroll
        for (int i = 0; i < 8; i++) { a += rs[i]; b += rs2[i]; }
        float mu = a * (1.0f / En);
        float var = b * (1.0f / En) - mu * mu;
        smu = mu;
        sinv = rsqrtf(var + 1e-5f);
    }
    __syncthreads();
    const float mu = smu, inv = sinv;
    float4 g4 = ((const float4*)gamma)[tid];
    float4 b4 = ((const float4*)beta)[tid];
    float4 o4;
    o4.x = (v.x - mu) * inv * g4.x + b4.x;
    o4.y = (v.y - mu) * inv * g4.y + b4.y;
    o4.z = (v.z - mu) * inv * g4.z + b4.z;
    o4.w = (v.w - mu) * inv * g4.w + b4.w;
    ((float4*)(Y + (size_t)row * En))[tid] = o4;

    __nv_bfloat16 h[4], lo[4];
    split1(o4.x, h[0], lo[0]); split1(o4.y, h[1], lo[1]);
    split1(o4.z, h[2], lo[2]); split1(o4.w, h[3], lo[3]);
    ((uint2*)(Yhi + (size_t)row * En))[tid] = *(uint2*)h;
    ((uint2*)(Ylo + (size_t)row * En))[tid] = *(uint2*)lo;
}

// ---------------------------------------------------------------------------
// Fused logits GEMM (64 tokens x 64 outputs, K=1024) + softmax -> pi
// ---------------------------------------------------------------------------
__global__ __launch_bounds__(256)
void pi_softmax_kernel(const float* __restrict__ H, const float* __restrict__ Wt,
                       const float* __restrict__ bt, float* __restrict__ pi_out) {
    constexpr int TM = 64, TK = 32, PAD = 4;
    __shared__ float hs[TK][TM + PAD];
    __shared__ float ws[TK][TM + PAD];
    __shared__ float ls[64][65];

    const int t0 = blockIdx.x * TM;
    const int tid = threadIdx.x;
    const int tx = tid & 15, ty = tid >> 4;
    const int r0 = tid >> 3;
    const int c4 = (tid & 7) * 4;

    float acc[4][4];
#pragma unroll
    for (int i = 0; i < 4; i++)
#pragma unroll
        for (int j = 0; j < 4; j++) acc[i][j] = 0.0f;

    for (int kt = 0; kt < En / TK; kt++) {
        const int kb = kt * TK;
        float4 h0 = *(const float4*)&H[(size_t)(t0 + r0) * En + kb + c4];
        float4 h1 = *(const float4*)&H[(size_t)(t0 + r0 + 32) * En + kb + c4];
        float4 w0 = *(const float4*)&Wt[(size_t)r0 * En + kb + c4];
        float4 w1 = *(const float4*)&Wt[(size_t)(r0 + 32) * En + kb + c4];
        __syncthreads();
        hs[c4 + 0][r0] = h0.x; hs[c4 + 1][r0] = h0.y; hs[c4 + 2][r0] = h0.z; hs[c4 + 3][r0] = h0.w;
        hs[c4 + 0][r0 + 32] = h1.x; hs[c4 + 1][r0 + 32] = h1.y; hs[c4 + 2][r0 + 32] = h1.z; hs[c4 + 3][r0 + 32] = h1.w;
        ws[c4 + 0][r0] = w0.x; ws[c4 + 1][r0] = w0.y; ws[c4 + 2][r0] = w0.z; ws[c4 + 3][r0] = w0.w;
        ws[c4 + 0][r0 + 32] = w1.x; ws[c4 + 1][r0 + 32] = w1.y; ws[c4 + 2][r0 + 32] = w1.z; ws[c4 + 3][r0 + 32] = w1.w;
        __syncthreads();
#pragma unroll
        for (int k = 0; k < TK; k++) {
            float a[4], b[4];
            *(float4*)a = *(const float4*)&hs[k][ty * 4];
            *(float4*)b = *(const float4*)&ws[k][tx * 4];
#pragma unroll
            for (int i = 0; i < 4; i++)
#pragma unroll
                for (int j = 0; j < 4; j++)
                    acc[i][j] = fmaf(a[i], b[j], acc[i][j]);
        }
    }
    __syncthreads();
#pragma unroll
    for (int i = 0; i < 4; i++)
#pragma unroll
        for (int j = 0; j < 4; j++)
            ls[ty * 4 + i][tx * 4 + j] = acc[i][j] + bt[tx * 4 + j];
    __syncthreads();

    const int w = tid >> 5, l = tid & 31;
    for (int t = w; t < 64; t += 8) {
        float v0 = ls[t][l], v1 = ls[t][l + 32];
        float mx = fmaxf(v0, v1);
#pragma unroll
        for (int o = 16; o; o >>= 1) mx = fmaxf(mx, __shfl_xor_sync(0xffffffffu, mx, o));
        float e0 = expf(v0 - mx), e1 = expf(v1 - mx);
        float sm = e0 + e1;
#pragma unroll
        for (int o = 16; o; o >>= 1) sm += __shfl_xor_sync(0xffffffffu, sm, o);
        float inv = 1.0f / sm;
        pi_out[(size_t)(t0 + t) * Vn + l] = e0 * inv;
        pi_out[(size_t)(t0 + t) * Vn + l + 32] = e1 * inv;
    }
}

// ---------------------------------------------------------------------------
// Per-token Q assembly (theta has padded row stride NTp)
// ---------------------------------------------------------------------------
__global__ __launch_bounds__(256)
void q_kernel(const float* __restrict__ theta, const float* __restrict__ pi,
              float* __restrict__ qout) {
    const int t = blockIdx.x;
    const int tid = threadIdx.x;
    __shared__ float th[NTn];
    __shared__ float sp[Vn], rp[Vn];
    __shared__ float qs[Vn][Vn + 1];
    __shared__ float rsum[Vn][4];

    const float4* trow = (const float4*)(theta + (size_t)t * NTp);
    for (int i = tid; i < NTn / 4; i += 256) ((float4*)th)[i] = trow[i];
    if (tid < Vn) {
        float p = pi[(size_t)t * Vn + tid];
        float s = sqrtf(p);
        sp[tid] = s;
        rp[tid] = 1.0f / s;
    }
    __syncthreads();

    const int i = tid >> 2, c = tid & 3;
    const float ri = rp[i];
    float part = 0.0f;
#pragma unroll
    for (int jj = 0; jj < 16; jj++) {
        const int j = c + jj * 4;
        float q = 0.0f;
        if (j != i) {
            const int a = min(i, j), b = max(i, j);
            const int k = a * 63 - (a * (a - 1)) / 2 + (b - a - 1);
            q = th[k] * sp[j] * ri;
        }
        qs[i][j] = q;
        part += q;
    }
    rsum[i][c] = part;
    __syncthreads();
    if (c == 0) {
        qs[i][i] = -(rsum[i][0] + rsum[i][1] + rsum[i][2] + rsum[i][3]);
    }
    __syncthreads();

    float* o = qout + (size_t)t * Vn * Vn;
#pragma unroll
    for (int r = 0; r < 4; r++) {
        const int e4 = tid + r * 256;
        const int e = e4 * 4;
        const int ii = e >> 6, j = e & 63;
        float4 v = make_float4(qs[ii][j], qs[ii][j + 1], qs[ii][j + 2], qs[ii][j + 3]);
        ((float4*)o)[e4] = v;
    }
}

// ---------------------------------------------------------------------------
extern "C" void kernel_launch(void* const* d_in, const int* in_sizes, int n_in,
                              void* d_out, int out_size) {
    const float* hx = (const float*)d_in[0];
    const float* Wd = (const float*)d_in[1];
    const float* bd = (const float*)d_in[2];
    const float* lng = (const float*)d_in[3];
    const float* lnb = (const float*)d_in[4];
    const float* Wt = (const float*)d_in[5];
    const float* bt = (const float*)d_in[6];
    const float* WT = (const float*)d_in[7];
    const float* bT = (const float*)d_in[8];

    float* out = (float*)d_out;
    float* qout = out;                                  // (B,L,V,V)
    float* piout = out + (size_t)Mn * Vn * Vn;          // (B,L,V)

    void* p;
    cudaGetSymbolAddress(&p, g_hx_hi);  __nv_bfloat16* hxh = (__nv_bfloat16*)p;
    cudaGetSymbolAddress(&p, g_hx_lo);  __nv_bfloat16* hxl = (__nv_bfloat16*)p;
    cudaGetSymbolAddress(&p, g_Wd_hi);  __nv_bfloat16* wdh = (__nv_bfloat16*)p;
    cudaGetSymbolAddress(&p, g_Wd_lo);  __nv_bfloat16* wdl = (__nv_bfloat16*)p;
    cudaGetSymbolAddress(&p, g_WT_hi);  __nv_bfloat16* wth = (__nv_bfloat16*)p;
    cudaGetSymbolAddress(&p, g_WT_lo);  __nv_bfloat16* wtl = (__nv_bfloat16*)p;
    cudaGetSymbolAddress(&p, g_H_hi);   __nv_bfloat16* hh = (__nv_bfloat16*)p;
    cudaGetSymbolAddress(&p, g_H_lo);   __nv_bfloat16* hl = (__nv_bfloat16*)p;
    cudaGetSymbolAddress(&p, g_act);    float* gact = (float*)p;
    cudaGetSymbolAddress(&p, g_hidden); float* gh = (float*)p;
    cudaGetSymbolAddress(&p, g_theta);  float* gth = (float*)p;

    cudaFuncSetAttribute(gemm_mma_kernel<1>, cudaFuncAttributeMaxDynamicSharedMemorySize,
                         gm::SMEM_BYTES);
    cudaFuncSetAttribute(gemm_mma_kernel<2>, cudaFuncAttributeMaxDynamicSharedMemorySize,
                         gm::SMEM_BYTES);

    dim3 blk(256);

    // 0) split conversions
    cvt_split_kernel<<<2048, blk>>>(hx, hxh, hxl, Mn * En / 4);
    cvt_split_kernel<<<1024, blk>>>(Wd, wdh, wdl, En * En / 4);
    cvt_split_pad_kernel<<<1024, blk>>>(WT, wth, wtl, NTn, NTp, En);

    // 1) dense + gelu  (M=8192, N=1024)
    {
        dim3 grid(En / 128, Mn / 128);  // (8, 64)
        gemm_mma_kernel<1><<<grid, blk, gm::SMEM_BYTES>>>(hxh, hxl, wdh, wdl, bd, gact,
                                                          En, En);
    }

    // 2) LayerNorm + split
    ln_split_kernel<<<Mn, blk>>>(gact, gh, hh, hl, lng, lnb);

    // 3) logits + softmax -> pi (written directly into output)
    pi_softmax_kernel<<<Mn / 64, blk>>>(gh, Wt, bt, piout);

    // 4) Theta projection + softplus (M=8192, Npad=2048)
    {
        dim3 grid(NTp / 128, Mn / 128);  // (16, 64)
        gemm_mma_kernel<2><<<grid, blk, gm::SMEM_BYTES>>>(hh, hl, wth, wtl, bT, gth,
                                                          NTn, NTp);
    }

    // 5) Q assembly
    q_kernel<<<Mn, blk>>>(gth, piout, qout);
}

// round 12
// speedup vs baseline: 2.1929x; 1.0092x over previous
#include <cuda_runtime.h>
#include <cuda_bf16.h>
#include <math.h>
#include <stdint.h>

// ---------------------------------------------------------------------------
// Problem constants
// ---------------------------------------------------------------------------
namespace {
constexpr int Bn = 4, Ln = 2048, En = 1024, Vn = 64, NTn = 2016;
constexpr int Mn = Bn * Ln;          // 8192 tokens
constexpr int NTp = 2048;            // padded Theta output dim
}

// ---------------------------------------------------------------------------
// Scratch (static device globals — no runtime allocation)
// ---------------------------------------------------------------------------
__device__ __nv_bfloat16 g_hx_hi[(size_t)Mn * En];
__device__ __nv_bfloat16 g_hx_lo[(size_t)Mn * En];
__device__ __nv_bfloat16 g_Wd_hi[(size_t)En * En];
__device__ __nv_bfloat16 g_Wd_lo[(size_t)En * En];
__device__ __nv_bfloat16 g_WT_hi[(size_t)NTp * En];   // padded, rows >=2016 zero
__device__ __nv_bfloat16 g_WT_lo[(size_t)NTp * En];
__device__ __nv_bfloat16 g_H_hi[(size_t)Mn * En];
__device__ __nv_bfloat16 g_H_lo[(size_t)Mn * En];
__device__ float g_act[(size_t)Mn * En];      // gelu(dense) output f32
__device__ float g_hidden[(size_t)Mn * En];   // LayerNorm output f32
__device__ float g_theta[(size_t)Mn * NTp];   // softplus(Theta), padded stride

__device__ __forceinline__ float gelu_exact(float x) {
    return 0.5f * x * (1.0f + erff(x * 0.7071067811865476f));
}
__device__ __forceinline__ float softplus_f(float x) {
    if (x > 20.0f) return x;
    return log1pf(expf(x));
}

__device__ __forceinline__ uint32_t smem_to_u32(const void* p) {
    uint32_t a;
    asm("{ .reg .u64 t; cvta.to.shared.u64 t, %1; cvt.u32.u64 %0, t; }"
        : "=r"(a) : "l"(p));
    return a;
}

// ---------------------------------------------------------------------------
// mma.sync / ldmatrix / cp.async primitives (plain sm_80+ PTX, no 'a' features)
// ---------------------------------------------------------------------------
__device__ __forceinline__ void mma16816(float c[4], const uint32_t a[4],
                                         uint32_t b0, uint32_t b1) {
    asm volatile(
        "mma.sync.aligned.m16n8k16.row.col.f32.bf16.bf16.f32 "
        "{%0,%1,%2,%3}, {%4,%5,%6,%7}, {%8,%9}, {%0,%1,%2,%3};"
        : "+f"(c[0]), "+f"(c[1]), "+f"(c[2]), "+f"(c[3])
        : "r"(a[0]), "r"(a[1]), "r"(a[2]), "r"(a[3]), "r"(b0), "r"(b1));
}

__device__ __forceinline__ void ldm_x4(uint32_t r[4], uint32_t addr) {
    asm volatile("ldmatrix.sync.aligned.m8n8.x4.shared.b16 {%0,%1,%2,%3}, [%4];"
        : "=r"(r[0]), "=r"(r[1]), "=r"(r[2]), "=r"(r[3]) : "r"(addr));
}

__device__ __forceinline__ void cp16(uint32_t s, const void* g) {
    asm volatile("cp.async.cg.shared.global [%0], [%1], 16;" :: "r"(s), "l"(g));
}
#define CP_COMMIT() asm volatile("cp.async.commit_group;" ::: "memory")
#define CP_WAIT1()  asm volatile("cp.async.wait_group 1;" ::: "memory")
#define CP_WAIT0()  asm volatile("cp.async.wait_group 0;" ::: "memory")

// ---------------------------------------------------------------------------
// Split conversion: f32 -> bf16 hi + bf16 lo
// ---------------------------------------------------------------------------
__device__ __forceinline__ void split1(float v, __nv_bfloat16& h, __nv_bfloat16& l) {
    h = __float2bfloat16(v);
    l = __float2bfloat16(v - __bfloat162float(h));
}

__global__ __launch_bounds__(256)
void cvt_split_kernel(const float* __restrict__ src, __nv_bfloat16* __restrict__ hi,
                      __nv_bfloat16* __restrict__ lo, int n4) {
    for (int i = blockIdx.x * 256 + threadIdx.x; i < n4; i += gridDim.x * 256) {
        float4 v = ((const float4*)src)[i];
        __nv_bfloat16 h[4], l[4];
        split1(v.x, h[0], l[0]); split1(v.y, h[1], l[1]);
        split1(v.z, h[2], l[2]); split1(v.w, h[3], l[3]);
        ((uint2*)hi)[i] = *(uint2*)h;
        ((uint2*)lo)[i] = *(uint2*)l;
    }
}

// padded variant: rows >= rows_real are zero (cols multiple of 4)
__global__ __launch_bounds__(256)
void cvt_split_pad_kernel(const float* __restrict__ src, __nv_bfloat16* __restrict__ hi,
                          __nv_bfloat16* __restrict__ lo, int rows_real, int rows_pad,
                          int cols) {
    int n4 = rows_pad * cols / 4;
    int c4 = cols / 4;
    for (int i = blockIdx.x * 256 + threadIdx.x; i < n4; i += gridDim.x * 256) {
        int row = i / c4;
        float4 v = make_float4(0.f, 0.f, 0.f, 0.f);
        if (row < rows_real) {
            int col4 = i - row * c4;
            v = ((const float4*)src)[(size_t)row * c4 + col4];
        }
        __nv_bfloat16 h[4], l[4];
        split1(v.x, h[0], l[0]); split1(v.y, h[1], l[1]);
        split1(v.z, h[2], l[2]); split1(v.w, h[3], l[3]);
        ((uint2*)hi)[i] = *(uint2*)h;
        ((uint2*)lo)[i] = *(uint2*)l;
    }
}

// ---------------------------------------------------------------------------
// Split-bf16 HMMA GEMM:  C[m,n] = act( sum_k A[m,k]*B[n,k] + bias[n] )
// A: M x 1024 (hi/lo bf16), B: Npad x 1024 (hi/lo bf16). CTA tile 128x128,
// BK=32, 3-stage cp.async pipeline (depth-2 prefetch), 2 CTAs/SM, swizzled
// 64B smem rows. MMA passes reordered so consecutive MMAs never share an
// accumulator (no RAW stalls). K fixed = 1024.
// ---------------------------------------------------------------------------
namespace gm {
constexpr int ROWB = 64;            // 32 bf16, XOR-swizzled chunks
constexpr int TILE = 128 * ROWB;    // 8192 B, one 128-row subtile
constexpr int STAGE = 4 * TILE;     // A_hi, A_lo, B_hi, B_lo = 32768 B
constexpr int NSTG = 3;
constexpr int SMEM_BYTES = NSTG * STAGE;  // 98304
constexpr int NKT = 32;             // 1024 / 32
}

// swizzled byte offset within a 128x64B subtile
__device__ __forceinline__ uint32_t swz(uint32_t row, uint32_t ch) {
    return row * 64u + ((ch ^ ((row >> 1) & 3u)) << 4);
}

template <int ACT>  // 1 gelu, 2 softplus
__global__ __launch_bounds__(256, 2)
void gemm_mma_kernel(const __nv_bfloat16* __restrict__ Ah, const __nv_bfloat16* __restrict__ Al,
                     const __nv_bfloat16* __restrict__ Bh, const __nv_bfloat16* __restrict__ Bl,
                     const float* __restrict__ bias, float* __restrict__ C,
                     int Nreal, int strideN) {
    extern __shared__ char smem[];
    const uint32_t sb = smem_to_u32(smem);
    const int tid = threadIdx.x, wid = tid >> 5, lane = tid & 31;
    const int m0 = blockIdx.y * 128, n0 = blockIdx.x * 128;
    const int wm = (wid & 1) * 64, wn = (wid >> 1) * 32;

    const __nv_bfloat16* srcs[4] = {Ah, Al, Bh, Bl};

    // per-thread copy slots (swizzled smem dst hoisted; gmem base hoisted)
    uint32_t cp_sa[8];
    const __nv_bfloat16* cp_g[8];
#pragma unroll
    for (int r = 0; r < 8; r++) {
        int idx = r * 256 + tid;          // 0..2047
        int sub = idx >> 9;               // 0..3
        uint32_t row = (idx >> 2) & 127;
        uint32_t ch = idx & 3;            // 16B chunk within 64B row
        cp_g[r] = srcs[sub] + (size_t)((sub < 2 ? m0 : n0) + row) * 1024 + ch * 8;
        cp_sa[r] = sb + sub * gm::TILE + swz(row, ch);
    }
    auto copy_stage = [&](int kt, int s) {
        const int kb = kt * 32;
        const uint32_t so = (uint32_t)s * gm::STAGE;
#pragma unroll
        for (int r = 0; r < 8; r++) cp16(cp_sa[r] + so, cp_g[r] + kb);
    };

    // per-warp ldmatrix addressing: row and swizzle-select per fragment group
    const uint32_t hi16 = (lane >> 4);         // 0/1: +16B column within k16 slice
    uint32_t a_off[2][4], b_off[2][2];
#pragma unroll
    for (int mi = 0; mi < 4; mi++) {
        uint32_t row = (uint32_t)(wm + mi * 16 + (lane & 15));
#pragma unroll
        for (int ks = 0; ks < 2; ks++)
            a_off[ks][mi] = swz(row, ks * 2 + hi16);
    }
#pragma unroll
    for (int g = 0; g < 2; g++) {
        uint32_t row = (uint32_t)(wn + g * 16 + ((lane >> 3) & 1) * 8 + (lane & 7));
#pragma unroll
        for (int ks = 0; ks < 2; ks++)
            b_off[ks][g] = swz(row, ks * 2 + hi16);
    }

    float acc[4][4][4];
#pragma unroll
    for (int mi = 0; mi < 4; mi++)
#pragma unroll
        for (int ni = 0; ni < 4; ni++)
#pragma unroll
            for (int e = 0; e < 4; e++) acc[mi][ni][e] = 0.0f;

    copy_stage(0, 0); CP_COMMIT();
    copy_stage(1, 1); CP_COMMIT();

    int scur = 0, scpy = 2;
    for (int kt = 0; kt < gm::NKT; kt++) {
        if (kt + 1 < gm::NKT) { CP_WAIT1(); } else { CP_WAIT0(); }
        __syncthreads();  // copy(kt) visible; compute(kt-1) done by all warps
        if (kt + 2 < gm::NKT) {
            copy_stage(kt + 2, scpy);
            CP_COMMIT();
            if (++scpy == gm::NSTG) scpy = 0;
        }

        const uint32_t Ahs = sb + (uint32_t)scur * gm::STAGE;
        const uint32_t Als = Ahs + gm::TILE;
        const uint32_t Bhs = Ahs + 2 * gm::TILE;
        const uint32_t Bls = Ahs + 3 * gm::TILE;
        if (++scur == gm::NSTG) scur = 0;

#pragma unroll
        for (int ks = 0; ks < 2; ks++) {       // two k16 slices
            uint32_t ah[4][4], al[4][4], bh[2][4], bl[2][4];
#pragma unroll
            for (int mi = 0; mi < 4; mi++) {
                ldm_x4(ah[mi], Ahs + a_off[ks][mi]);
                ldm_x4(al[mi], Als + a_off[ks][mi]);
            }
#pragma unroll
            for (int g = 0; g < 2; g++) {
                ldm_x4(bh[g], Bhs + b_off[ks][g]);
                ldm_x4(bl[g], Bls + b_off[ks][g]);
            }
            // Pass 1: hi*hi over all 16 independent accumulators
#pragma unroll
            for (int mi = 0; mi < 4; mi++)
#pragma unroll
                for (int ni = 0; ni < 4; ni++) {
                    const int g = ni >> 1, u = ni & 1;
                    mma16816(acc[mi][ni], ah[mi], bh[g][u], bh[g][u + 2]);
                }
            // Pass 2: hi*lo
#pragma unroll
            for (int mi = 0; mi < 4; mi++)
#pragma unroll
                for (int ni = 0; ni < 4; ni++) {
                    const int g = ni >> 1, u = ni & 1;
                    mma16816(acc[mi][ni], ah[mi], bl[g][u], bl[g][u + 2]);
                }
            // Pass 3: lo*hi
#pragma unroll
            for (int mi = 0; mi < 4; mi++)
#pragma unroll
                for (int ni = 0; ni < 4; ni++) {
                    const int g = ni >> 1, u = ni & 1;
                    mma16816(acc[mi][ni], al[mi], bh[g][u], bh[g][u + 2]);
                }
        }
    }

    // epilogue: bias + activation + float2 stores
    const int rr = lane >> 2, cc = (lane & 3) * 2;
#pragma unroll
    for (int mi = 0; mi < 4; mi++) {
        const int m = m0 + wm + mi * 16 + rr;
#pragma unroll
        for (int ni = 0; ni < 4; ni++) {
            const int n = n0 + wn + ni * 8 + cc;
            float b0v = (n < Nreal) ? bias[n] : 0.0f;
            float b1v = (n + 1 < Nreal) ? bias[n + 1] : 0.0f;
            float v0 = acc[mi][ni][0] + b0v;
            float v1 = acc[mi][ni][1] + b1v;
            float v2 = acc[mi][ni][2] + b0v;
            float v3 = acc[mi][ni][3] + b1v;
            if (ACT == 1) {
                v0 = gelu_exact(v0); v1 = gelu_exact(v1);
                v2 = gelu_exact(v2); v3 = gelu_exact(v3);
            } else {
                v0 = softplus_f(v0); v1 = softplus_f(v1);
                v2 = softplus_f(v2); v3 = softplus_f(v3);
            }
            float2 p0 = make_float2(v0, v1);
            float2 p1 = make_float2(v2, v3);
            *(float2*)&C[(size_t)m * strideN + n] = p0;
            *(float2*)&C[(size_t)(m + 8) * strideN + n] = p1;
        }
    }
}

// ---------------------------------------------------------------------------
// Row LayerNorm over E=1024, fused bf16 hi/lo split output.
// ---------------------------------------------------------------------------
__global__ __launch_bounds__(256)
void ln_split_kernel(const float* __restrict__ X, float* __restrict__ Y,
                     __nv_bfloat16* __restrict__ Yhi, __nv_bfloat16* __restrict__ Ylo,
                     const float* __restrict__ gamma, const float* __restrict__ beta) {
    const int row = blockIdx.x;
    const int tid = threadIdx.x;
    const float4* x = (const float4*)(X + (size_t)row * En);

    float4 v = x[tid];
    float s = v.x + v.y + v.z + v.w;
    float s2 = v.x * v.x + v.y * v.y + v.z * v.z + v.w * v.w;
#pragma unroll
    for (int o = 16; o; o >>= 1) {
        s += __shfl_xor_sync(0xffffffffu, s, o);
        s2 += __shfl_xor_sync(0xffffffffu, s2, o);
    }
    __shared__ float rs[8], rs2[8];
    __shared__ float smu, sinv;
    const int w = tid >> 5, l = tid & 31;
    if (l == 0) { rs[w] = s; rs2[w] = s2; }
    __syncthreads();
    if (tid == 0) {
        float a = 0.f, b = 0.f;
#pragma unroll
        for (int i = 0; i < 8; i++) { a += rs[i]; b += rs2[i]; }
        float mu = a * (1.0f / En);
        float var = b * (1.0f / En) - mu * mu;
        smu = mu;
        sinv = rsqrtf(var + 1e-5f);
    }
    __syncthreads();
    const float mu = smu, inv = sinv;
    float4 g4 = ((const float4*)gamma)[tid];
    float4 b4 = ((const float4*)beta)[tid];
    float4 o4;
    o4.x = (v.x - mu) * inv * g4.x + b4.x;
    o4.y = (v.y - mu) * inv * g4.y + b4.y;
    o4.z = (v.z - mu) * inv * g4.z + b4.z;
    o4.w = (v.w - mu) * inv * g4.w + b4.w;
    ((float4*)(Y + (size_t)row * En))[tid] = o4;

    __nv_bfloat16 h[4], lo[4];
    split1(o4.x, h[0], lo[0]); split1(o4.y, h[1], lo[1]);
    split1(o4.z, h[2], lo[2]); split1(o4.w, h[3], lo[3]);
    ((uint2*)(Yhi + (size_t)row * En))[tid] = *(uint2*)h;
    ((uint2*)(Ylo + (size_t)row * En))[tid] = *(uint2*)lo;
}

// ---------------------------------------------------------------------------
// Fused logits GEMM (64 tokens x 64 outputs, K=1024) + softmax -> pi
// ---------------------------------------------------------------------------
__global__ __launch_bounds__(256)
void pi_softmax_kernel(const float* __restrict__ H, const float* __restrict__ Wt,
                       const float* __restrict__ bt, float* __restrict__ pi_out) {
    constexpr int TM = 64, TK = 32, PAD = 4;
    __shared__ float hs[TK][TM + PAD];
    __shared__ float ws[TK][TM + PAD];
    __shared__ float ls[64][65];

    const int t0 = blockIdx.x * TM;
    const int tid = threadIdx.x;
    const int tx = tid & 15, ty = tid >> 4;
    const int r0 = tid >> 3;
    const int c4 = (tid & 7) * 4;

    float acc[4][4];
#pragma unroll
    for (int i = 0; i < 4; i++)
#pragma unroll
        for (int j = 0; j < 4; j++) acc[i][j] = 0.0f;

    for (int kt = 0; kt < En / TK; kt++) {
        const int kb = kt * TK;
        float4 h0 = *(const float4*)&H[(size_t)(t0 + r0) * En + kb + c4];
        float4 h1 = *(const float4*)&H[(size_t)(t0 + r0 + 32) * En + kb + c4];
        float4 w0 = *(const float4*)&Wt[(size_t)r0 * En + kb + c4];
        float4 w1 = *(const float4*)&Wt[(size_t)(r0 + 32) * En + kb + c4];
        __syncthreads();
        hs[c4 + 0][r0] = h0.x; hs[c4 + 1][r0] = h0.y; hs[c4 + 2][r0] = h0.z; hs[c4 + 3][r0] = h0.w;
        hs[c4 + 0][r0 + 32] = h1.x; hs[c4 + 1][r0 + 32] = h1.y; hs[c4 + 2][r0 + 32] = h1.z; hs[c4 + 3][r0 + 32] = h1.w;
        ws[c4 + 0][r0] = w0.x; ws[c4 + 1][r0] = w0.y; ws[c4 + 2][r0] = w0.z; ws[c4 + 3][r0] = w0.w;
        ws[c4 + 0][r0 + 32] = w1.x; ws[c4 + 1][r0 + 32] = w1.y; ws[c4 + 2][r0 + 32] = w1.z; ws[c4 + 3][r0 + 32] = w1.w;
        __syncthreads();
#pragma unroll
        for (int k = 0; k < TK; k++) {
            float a[4], b[4];
            *(float4*)a = *(const float4*)&hs[k][ty * 4];
            *(float4*)b = *(const float4*)&ws[k][tx * 4];
#pragma unroll
            for (int i = 0; i < 4; i++)
#pragma unroll
                for (int j = 0; j < 4; j++)
                    acc[i][j] = fmaf(a[i], b[j], acc[i][j]);
        }
    }
    __syncthreads();
#pragma unroll
    for (int i = 0; i < 4; i++)
#pragma unroll
        for (int j = 0; j < 4; j++)
            ls[ty * 4 + i][tx * 4 + j] = acc[i][j] + bt[tx * 4 + j];
    __syncthreads();

    const int w = tid >> 5, l = tid & 31;
    for (int t = w; t < 64; t += 8) {
        float v0 = ls[t][l], v1 = ls[t][l + 32];
        float mx = fmaxf(v0, v1);
#pragma unroll
        for (int o = 16; o; o >>= 1) mx = fmaxf(mx, __shfl_xor_sync(0xffffffffu, mx, o));
        float e0 = expf(v0 - mx), e1 = expf(v1 - mx);
        float sm = e0 + e1;
#pragma unroll
        for (int o = 16; o; o >>= 1) sm += __shfl_xor_sync(0xffffffffu, sm, o);
        float inv = 1.0f / sm;
        pi_out[(size_t)(t0 + t) * Vn + l] = e0 * inv;
        pi_out[(size_t)(t0 + t) * Vn + l + 32] = e1 * inv;
    }
}

// ---------------------------------------------------------------------------
// Per-token Q assembly (theta has padded row stride NTp)
// ---------------------------------------------------------------------------
__global__ __launch_bounds__(256)
void q_kernel(const float* __restrict__ theta, const float* __restrict__ pi,
              float* __restrict__ qout) {
    const int t = blockIdx.x;
    const int tid = threadIdx.x;
    __shared__ float th[NTn];
    __shared__ float sp[Vn], rp[Vn];
    __shared__ float qs[Vn][Vn + 1];
    __shared__ float rsum[Vn][4];

    const float4* trow = (const float4*)(theta + (size_t)t * NTp);
    for (int i = tid; i < NTn / 4; i += 256) ((float4*)th)[i] = trow[i];
    if (tid < Vn) {
        float p = pi[(size_t)t * Vn + tid];
        float s = sqrtf(p);
        sp[tid] = s;
        rp[tid] = 1.0f / s;
    }
    __syncthreads();

    const int i = tid >> 2, c = tid & 3;
    const float ri = rp[i];
    float part = 0.0f;
#pragma unroll
    for (int jj = 0; jj < 16; jj++) {
        const int j = c + jj * 4;
        float q = 0.0f;
        if (j != i) {
            const int a = min(i, j), b = max(i, j);
            const int k = a * 63 - (a * (a - 1)) / 2 + (b - a - 1);
            q = th[k] * sp[j] * ri;
        }
        qs[i][j] = q;
        part += q;
    }
    rsum[i][c] = part;
    __syncthreads();
    if (c == 0) {
        qs[i][i] = -(rsum[i][0] + rsum[i][1] + rsum[i][2] + rsum[i][3]);
    }
    __syncthreads();

    float* o = qout + (size_t)t * Vn * Vn;
#pragma unroll
    for (int r = 0; r < 4; r++) {
        const int e4 = tid + r * 256;
        const int e = e4 * 4;
        const int ii = e >> 6, j = e & 63;
        float4 v = make_float4(qs[ii][j], qs[ii][j + 1], qs[ii][j + 2], qs[ii][j + 3]);
        ((float4*)o)[e4] = v;
    }
}

// ---------------------------------------------------------------------------
extern "C" void kernel_launch(void* const* d_in, const int* in_sizes, int n_in,
                              void* d_out, int out_size) {
    const float* hx = (const float*)d_in[0];
    const float* Wd = (const float*)d_in[1];
    const float* bd = (const float*)d_in[2];
    const float* lng = (const float*)d_in[3];
    const float* lnb = (const float*)d_in[4];
    const float* Wt = (const float*)d_in[5];
    const float* bt = (const float*)d_in[6];
    const float* WT = (const float*)d_in[7];
    const float* bT = (const float*)d_in[8];

    float* out = (float*)d_out;
    float* qout = out;                                  // (B,L,V,V)
    float* piout = out + (size_t)Mn * Vn * Vn;          // (B,L,V)

    void* p;
    cudaGetSymbolAddress(&p, g_hx_hi);  __nv_bfloat16* hxh = (__nv_bfloat16*)p;
    cudaGetSymbolAddress(&p, g_hx_lo);  __nv_bfloat16* hxl = (__nv_bfloat16*)p;
    cudaGetSymbolAddress(&p, g_Wd_hi);  __nv_bfloat16* wdh = (__nv_bfloat16*)p;
    cudaGetSymbolAddress(&p, g_Wd_lo);  __nv_bfloat16* wdl = (__nv_bfloat16*)p;
    cudaGetSymbolAddress(&p, g_WT_hi);  __nv_bfloat16* wth = (__nv_bfloat16*)p;
    cudaGetSymbolAddress(&p, g_WT_lo);  __nv_bfloat16* wtl = (__nv_bfloat16*)p;
    cudaGetSymbolAddress(&p, g_H_hi);   __nv_bfloat16* hh = (__nv_bfloat16*)p;
    cudaGetSymbolAddress(&p, g_H_lo);   __nv_bfloat16* hl = (__nv_bfloat16*)p;
    cudaGetSymbolAddress(&p, g_act);    float* gact = (float*)p;
    cudaGetSymbolAddress(&p, g_hidden); float* gh = (float*)p;
    cudaGetSymbolAddress(&p, g_theta);  float* gth = (float*)p;

    cudaFuncSetAttribute(gemm_mma_kernel<1>, cudaFuncAttributeMaxDynamicSharedMemorySize,
                         gm::SMEM_BYTES);
    cudaFuncSetAttribute(gemm_mma_kernel<2>, cudaFuncAttributeMaxDynamicSharedMemorySize,
                         gm::SMEM_BYTES);

    dim3 blk(256);

    // 0) split conversions
    cvt_split_kernel<<<2048, blk>>>(hx, hxh, hxl, Mn * En / 4);
    cvt_split_kernel<<<1024, blk>>>(Wd, wdh, wdl, En * En / 4);
    cvt_split_pad_kernel<<<1024, blk>>>(WT, wth, wtl, NTn, NTp, En);

    // 1) dense + gelu  (M=8192, N=1024)
    {
        dim3 grid(En / 128, Mn / 128);  // (8, 64)
        gemm_mma_kernel<1><<<grid, blk, gm::SMEM_BYTES>>>(hxh, hxl, wdh, wdl, bd, gact,
                                                          En, En);
    }

    // 2) LayerNorm + split
    ln_split_kernel<<<Mn, blk>>>(gact, gh, hh, hl, lng, lnb);

    // 3) logits + softmax -> pi (written directly into output)
    pi_softmax_kernel<<<Mn / 64, blk>>>(gh, Wt, bt, piout);

    // 4) Theta projection + softplus (M=8192, Npad=2048)
    {
        dim3 grid(NTp / 128, Mn / 128);  // (16, 64)
        gemm_mma_kernel<2><<<grid, blk, gm::SMEM_BYTES>>>(hh, hl, wth, wtl, bT, gth,
                                                          NTn, NTp);
    }

    // 5) Q assembly
    q_kernel<<<Mn, blk>>>(gth, piout, qout);
}

// round 15
// speedup vs baseline: 2.9602x; 1.3499x over previous
#include <cuda_runtime.h>
#include <cuda_fp16.h>
#include <math.h>
#include <stdint.h>

// ---------------------------------------------------------------------------
// Problem constants
// ---------------------------------------------------------------------------
namespace {
constexpr int Bn = 4, Ln = 2048, En = 1024, Vn = 64, NTn = 2016;
constexpr int Mn = Bn * Ln;          // 8192 tokens
constexpr int NTp = 2048;            // padded Theta output dim
}

// ---------------------------------------------------------------------------
// Scratch (static device globals — no runtime allocation)
// ---------------------------------------------------------------------------
__device__ __half g_hx_hi[(size_t)Mn * En];
__device__ __half g_Wd_hi[(size_t)En * En];
__device__ __half g_Wd_lo[(size_t)En * En];
__device__ __half g_WT_hi[(size_t)NTp * En];   // padded, rows >=2016 zero
__device__ __half g_WT_lo[(size_t)NTp * En];
__device__ __half g_H_hi[(size_t)Mn * En];
__device__ float g_act[(size_t)Mn * En];      // gelu(dense) output f32
__device__ float g_hidden[(size_t)Mn * En];   // LayerNorm output f32
__device__ float g_theta[(size_t)Mn * NTp];   // softplus(Theta), padded stride

__device__ __forceinline__ float gelu_exact(float x) {
    return 0.5f * x * (1.0f + erff(x * 0.7071067811865476f));
}
__device__ __forceinline__ float softplus_f(float x) {
    if (x > 20.0f) return x;
    return log1pf(expf(x));
}

__device__ __forceinline__ uint32_t smem_to_u32(const void* p) {
    uint32_t a;
    asm("{ .reg .u64 t; cvta.to.shared.u64 t, %1; cvt.u32.u64 %0, t; }"
        : "=r"(a) : "l"(p));
    return a;
}

// ---------------------------------------------------------------------------
// mma.sync / ldmatrix / cp.async primitives (plain sm_80+ PTX, no 'a' features)
// ---------------------------------------------------------------------------
__device__ __forceinline__ void mma16816(float c[4], const uint32_t a[4],
                                         uint32_t b0, uint32_t b1) {
    asm volatile(
        "mma.sync.aligned.m16n8k16.row.col.f32.f16.f16.f32 "
        "{%0,%1,%2,%3}, {%4,%5,%6,%7}, {%8,%9}, {%0,%1,%2,%3};"
        : "+f"(c[0]), "+f"(c[1]), "+f"(c[2]), "+f"(c[3])
        : "r"(a[0]), "r"(a[1]), "r"(a[2]), "r"(a[3]), "r"(b0), "r"(b1));
}

__device__ __forceinline__ void ldm_x4(uint32_t r[4], uint32_t addr) {
    asm volatile("ldmatrix.sync.aligned.m8n8.x4.shared.b16 {%0,%1,%2,%3}, [%4];"
        : "=r"(r[0]), "=r"(r[1]), "=r"(r[2]), "=r"(r[3]) : "r"(addr));
}

__device__ __forceinline__ void cp16(uint32_t s, const void* g) {
    asm volatile("cp.async.cg.shared.global [%0], [%1], 16;" :: "r"(s), "l"(g));
}
#define CP_COMMIT() asm volatile("cp.async.commit_group;" ::: "memory")
#define CP_WAIT2()  asm volatile("cp.async.wait_group 2;" ::: "memory")
#define CP_WAIT1()  asm volatile("cp.async.wait_group 1;" ::: "memory")
#define CP_WAIT0()  asm volatile("cp.async.wait_group 0;" ::: "memory")

// ---------------------------------------------------------------------------
// Split conversion: f32 -> f16 hi (+ f16 lo)
// ---------------------------------------------------------------------------
__device__ __forceinline__ void split1h(float v, __half& h, __half& l) {
    h = __float2half(v);
    l = __float2half(v - __half2float(h));
}

__global__ __launch_bounds__(256)
void cvt_hi_kernel(const float* __restrict__ src, __half* __restrict__ hi, int n4) {
    for (int i = blockIdx.x * 256 + threadIdx.x; i < n4; i += gridDim.x * 256) {
        float4 v = ((const float4*)src)[i];
        __half h[4];
        h[0] = __float2half(v.x); h[1] = __float2half(v.y);
        h[2] = __float2half(v.z); h[3] = __float2half(v.w);
        ((uint2*)hi)[i] = *(uint2*)h;
    }
}

__global__ __launch_bounds__(256)
void cvt_split_kernel(const float* __restrict__ src, __half* __restrict__ hi,
                      __half* __restrict__ lo, int n4) {
    for (int i = blockIdx.x * 256 + threadIdx.x; i < n4; i += gridDim.x * 256) {
        float4 v = ((const float4*)src)[i];
        __half h[4], l[4];
        split1h(v.x, h[0], l[0]); split1h(v.y, h[1], l[1]);
        split1h(v.z, h[2], l[2]); split1h(v.w, h[3], l[3]);
        ((uint2*)hi)[i] = *(uint2*)h;
        ((uint2*)lo)[i] = *(uint2*)l;
    }
}

// padded variant: rows >= rows_real are zero (cols multiple of 4)
__global__ __launch_bounds__(256)
void cvt_split_pad_kernel(const float* __restrict__ src, __half* __restrict__ hi,
                          __half* __restrict__ lo, int rows_real, int rows_pad,
                          int cols) {
    int n4 = rows_pad * cols / 4;
    int c4 = cols / 4;
    for (int i = blockIdx.x * 256 + threadIdx.x; i < n4; i += gridDim.x * 256) {
        int row = i / c4;
        float4 v = make_float4(0.f, 0.f, 0.f, 0.f);
        if (row < rows_real) {
            int col4 = i - row * c4;
            v = ((const float4*)src)[(size_t)row * c4 + col4];
        }
        __half h[4], l[4];
        split1h(v.x, h[0], l[0]); split1h(v.y, h[1], l[1]);
        split1h(v.z, h[2], l[2]); split1h(v.w, h[3], l[3]);
        ((uint2*)hi)[i] = *(uint2*)h;
        ((uint2*)lo)[i] = *(uint2*)l;
    }
}

// ---------------------------------------------------------------------------
// Split-fp16 HMMA GEMM:  C[m,n] = act( sum_k A[m,k]*B[n,k] + bias[n] )
// A: M x 1024 (f16 hi only), B: Npad x 1024 (f16 hi/lo). CTA tile 128x128,
// BK=32, 4-stage cp.async pipeline (depth-3 prefetch), 2 CTAs/SM, swizzled
// 64B smem rows. Two MMA terms: ah*bh + ah*bl (al*bh dropped, ~2^-12 rel).
// ---------------------------------------------------------------------------
namespace gm {
constexpr int ROWB = 64;            // 32 f16, XOR-swizzled 16B chunks
constexpr int TILE = 128 * ROWB;    // 8192 B, one 128-row subtile
constexpr int STAGE = 3 * TILE;     // A_hi, B_hi, B_lo = 24576 B
constexpr int NSTG = 4;
constexpr int SMEM_BYTES = NSTG * STAGE;  // 98304
constexpr int NKT = 32;             // 1024 / 32
}

// swizzled byte offset within a 128x64B subtile
__device__ __forceinline__ uint32_t swz(uint32_t row, uint32_t ch) {
    return row * 64u + ((ch ^ ((row >> 1) & 3u)) << 4);
}

template <int ACT>  // 1 gelu, 2 softplus
__global__ __launch_bounds__(256, 2)
void gemm_mma_kernel(const __half* __restrict__ Ah,
                     const __half* __restrict__ Bh, const __half* __restrict__ Bl,
                     const float* __restrict__ bias, float* __restrict__ C,
                     int Nreal, int strideN) {
    extern __shared__ char smem[];
    const uint32_t sb = smem_to_u32(smem);
    const int tid = threadIdx.x, wid = tid >> 5, lane = tid & 31;
    const int m0 = blockIdx.y * 128, n0 = blockIdx.x * 128;
    const int wm = (wid & 1) * 64, wn = (wid >> 1) * 32;

    const __half* srcs[3] = {Ah, Bh, Bl};

    // per-thread copy slots: 3 subtiles x 128 rows x 4 chunks = 1536 -> 6/thread
    uint32_t cp_sa[6];
    const __half* cp_g[6];
#pragma unroll
    for (int r = 0; r < 6; r++) {
        int idx = r * 256 + tid;          // 0..1535
        int sub = idx >> 9;               // 0..2
        uint32_t row = (idx >> 2) & 127;
        uint32_t ch = idx & 3;            // 16B chunk within 64B row
        cp_g[r] = srcs[sub] + (size_t)((sub == 0 ? m0 : n0) + row) * 1024 + ch * 8;
        cp_sa[r] = sb + sub * gm::TILE + swz(row, ch);
    }
    auto copy_stage = [&](int kt, int s) {
        const int kb = kt * 32;
        const uint32_t so = (uint32_t)s * gm::STAGE;
#pragma unroll
        for (int r = 0; r < 6; r++) cp16(cp_sa[r] + so, cp_g[r] + kb);
    };

    // per-warp ldmatrix addressing
    const uint32_t hi16 = (lane >> 4);         // 0/1: +16B column within k16 slice
    uint32_t a_off[2][4], b_off[2][2];
#pragma unroll
    for (int mi = 0; mi < 4; mi++) {
        uint32_t row = (uint32_t)(wm + mi * 16 + (lane & 15));
#pragma unroll
        for (int ks = 0; ks < 2; ks++)
            a_off[ks][mi] = swz(row, ks * 2 + hi16);
    }
#pragma unroll
    for (int g = 0; g < 2; g++) {
        uint32_t row = (uint32_t)(wn + g * 16 + ((lane >> 3) & 1) * 8 + (lane & 7));
#pragma unroll
        for (int ks = 0; ks < 2; ks++)
            b_off[ks][g] = swz(row, ks * 2 + hi16);
    }

    float acc[4][4][4];
#pragma unroll
    for (int mi = 0; mi < 4; mi++)
#pragma unroll
        for (int ni = 0; ni < 4; ni++)
#pragma unroll
            for (int e = 0; e < 4; e++) acc[mi][ni][e] = 0.0f;

    copy_stage(0, 0); CP_COMMIT();
    copy_stage(1, 1); CP_COMMIT();
    copy_stage(2, 2); CP_COMMIT();

    int scur = 0;
    for (int kt = 0; kt < gm::NKT; kt++) {
        const int rem = gm::NKT - 1 - kt;
        if (rem >= 2) { CP_WAIT2(); }
        else if (rem == 1) { CP_WAIT1(); }
        else { CP_WAIT0(); }
        __syncthreads();  // copies for kt visible to all; compute kt-1 done by all
        if (kt + 3 < gm::NKT) {
            copy_stage(kt + 3, (kt + 3) & 3);  // stage (kt-1)&3: compute done
            CP_COMMIT();
        }

        const uint32_t Ahs = sb + (uint32_t)scur * gm::STAGE;
        const uint32_t Bhs = Ahs + gm::TILE;
        const uint32_t Bls = Ahs + 2 * gm::TILE;
        if (++scur == gm::NSTG) scur = 0;

#pragma unroll
        for (int ks = 0; ks < 2; ks++) {       // two k16 slices
            uint32_t ah[4][4], bh[2][4], bl[2][4];
#pragma unroll
            for (int mi = 0; mi < 4; mi++) ldm_x4(ah[mi], Ahs + a_off[ks][mi]);
#pragma unroll
            for (int g = 0; g < 2; g++) {
                ldm_x4(bh[g], Bhs + b_off[ks][g]);
                ldm_x4(bl[g], Bls + b_off[ks][g]);
            }
            // Pass 1: hi*hi over 16 independent accumulators
#pragma unroll
            for (int mi = 0; mi < 4; mi++)
#pragma unroll
                for (int ni = 0; ni < 4; ni++) {
                    const int g = ni >> 1, u = ni & 1;
                    mma16816(acc[mi][ni], ah[mi], bh[g][u], bh[g][u + 2]);
                }
            // Pass 2: hi*lo
#pragma unroll
            for (int mi = 0; mi < 4; mi++)
#pragma unroll
                for (int ni = 0; ni < 4; ni++) {
                    const int g = ni >> 1, u = ni & 1;
                    mma16816(acc[mi][ni], ah[mi], bl[g][u], bl[g][u + 2]);
                }
        }
    }

    // epilogue: bias + activation + float2 stores
    const int rr = lane >> 2, cc = (lane & 3) * 2;
#pragma unroll
    for (int mi = 0; mi < 4; mi++) {
        const int m = m0 + wm + mi * 16 + rr;
#pragma unroll
        for (int ni = 0; ni < 4; ni++) {
            const int n = n0 + wn + ni * 8 + cc;
            float b0v = (n < Nreal) ? bias[n] : 0.0f;
            float b1v = (n + 1 < Nreal) ? bias[n + 1] : 0.0f;
            float v0 = acc[mi][ni][0] + b0v;
            float v1 = acc[mi][ni][1] + b1v;
            float v2 = acc[mi][ni][2] + b0v;
            float v3 = acc[mi][ni][3] + b1v;
            if (ACT == 1) {
                v0 = gelu_exact(v0); v1 = gelu_exact(v1);
                v2 = gelu_exact(v2); v3 = gelu_exact(v3);
            } else {
                v0 = softplus_f(v0); v1 = softplus_f(v1);
                v2 = softplus_f(v2); v3 = softplus_f(v3);
            }
            float2 p0 = make_float2(v0, v1);
            float2 p1 = make_float2(v2, v3);
            *(float2*)&C[(size_t)m * strideN + n] = p0;
            *(float2*)&C[(size_t)(m + 8) * strideN + n] = p1;
        }
    }
}

// ---------------------------------------------------------------------------
// Row LayerNorm over E=1024, fused f16-hi output for the next GEMM's A side.
// ---------------------------------------------------------------------------
__global__ __launch_bounds__(256)
void ln_split_kernel(const float* __restrict__ X, float* __restrict__ Y,
                     __half* __restrict__ Yhi,
                     const float* __restrict__ gamma, const float* __restrict__ beta) {
    const int row = blockIdx.x;
    const int tid = threadIdx.x;
    const float4* x = (const float4*)(X + (size_t)row * En);

    float4 v = x[tid];
    float s = v.x + v.y + v.z + v.w;
    float s2 = v.x * v.x + v.y * v.y + v.z * v.z + v.w * v.w;
#pragma unroll
    for (int o = 16; o; o >>= 1) {
        s += __shfl_xor_sync(0xffffffffu, s, o);
        s2 += __shfl_xor_sync(0xffffffffu, s2, o);
    }
    __shared__ float rs[8], rs2[8];
    __shared__ float smu, sinv;
    const int w = tid >> 5, l = tid & 31;
    if (l == 0) { rs[w] = s; rs2[w] = s2; }
    __syncthreads();
    if (tid == 0) {
        float a = 0.f, b = 0.f;
#pragma unroll
        for (int i = 0; i < 8; i++) { a += rs[i]; b += rs2[i]; }
        float mu = a * (1.0f / En);
        float var = b * (1.0f / En) - mu * mu;
        smu = mu;
        sinv = rsqrtf(var + 1e-5f);
    }
    __syncthreads();
    const float mu = smu, inv = sinv;
    float4 g4 = ((const float4*)gamma)[tid];
    float4 b4 = ((const float4*)beta)[tid];
    float4 o4;
    o4.x = (v.x - mu) * inv * g4.x + b4.x;
    o4.y = (v.y - mu) * inv * g4.y + b4.y;
    o4.z = (v.z - mu) * inv * g4.z + b4.z;
    o4.w = (v.w - mu) * inv * g4.w + b4.w;
    ((float4*)(Y + (size_t)row * En))[tid] = o4;

    __half h[4];
    h[0] = __float2half(o4.x); h[1] = __float2half(o4.y);
    h[2] = __float2half(o4.z); h[3] = __float2half(o4.w);
    ((uint2*)(Yhi + (size_t)row * En))[tid] = *(uint2*)h;
}

// ---------------------------------------------------------------------------
// Fused logits GEMM (64 tokens x 64 outputs, K=1024) + softmax -> pi
// ---------------------------------------------------------------------------
__global__ __launch_bounds__(256)
void pi_softmax_kernel(const float* __restrict__ H, const float* __restrict__ Wt,
                       const float* __restrict__ bt, float* __restrict__ pi_out) {
    constexpr int TM = 64, TK = 32, PAD = 4;
    __shared__ float hs[TK][TM + PAD];
    __shared__ float ws[TK][TM + PAD];
    __shared__ float ls[64][65];

    const int t0 = blockIdx.x * TM;
    const int tid = threadIdx.x;
    const int tx = tid & 15, ty = tid >> 4;
    const int r0 = tid >> 3;
    const int c4 = (tid & 7) * 4;

    float acc[4][4];
#pragma unroll
    for (int i = 0; i < 4; i++)
#pragma unroll
        for (int j = 0; j < 4; j++) acc[i][j] = 0.0f;

    for (int kt = 0; kt < En / TK; kt++) {
        const int kb = kt * TK;
        float4 h0 = *(const float4*)&H[(size_t)(t0 + r0) * En + kb + c4];
        float4 h1 = *(const float4*)&H[(size_t)(t0 + r0 + 32) * En + kb + c4];
        float4 w0 = *(const float4*)&Wt[(size_t)r0 * En + kb + c4];
        float4 w1 = *(const float4*)&Wt[(size_t)(r0 + 32) * En + kb + c4];
        __syncthreads();
        hs[c4 + 0][r0] = h0.x; hs[c4 + 1][r0] = h0.y; hs[c4 + 2][r0] = h0.z; hs[c4 + 3][r0] = h0.w;
        hs[c4 + 0][r0 + 32] = h1.x; hs[c4 + 1][r0 + 32] = h1.y; hs[c4 + 2][r0 + 32] = h1.z; hs[c4 + 3][r0 + 32] = h1.w;
        ws[c4 + 0][r0] = w0.x; ws[c4 + 1][r0] = w0.y; ws[c4 + 2][r0] = w0.z; ws[c4 + 3][r0] = w0.w;
        ws[c4 + 0][r0 + 32] = w1.x; ws[c4 + 1][r0 + 32] = w1.y; ws[c4 + 2][r0 + 32] = w1.z; ws[c4 + 3][r0 + 32] = w1.w;
        __syncthreads();
#pragma unroll
        for (int k = 0; k < TK; k++) {
            float a[4], b[4];
            *(float4*)a = *(const float4*)&hs[k][ty * 4];
            *(float4*)b = *(const float4*)&ws[k][tx * 4];
#pragma unroll
            for (int i = 0; i < 4; i++)
#pragma unroll
                for (int j = 0; j < 4; j++)
                    acc[i][j] = fmaf(a[i], b[j], acc[i][j]);
        }
    }
    __syncthreads();
#pragma unroll
    for (int i = 0; i < 4; i++)
#pragma unroll
        for (int j = 0; j < 4; j++)
            ls[ty * 4 + i][tx * 4 + j] = acc[i][j] + bt[tx * 4 + j];
    __syncthreads();

    const int w = tid >> 5, l = tid & 31;
    for (int t = w; t < 64; t += 8) {
        float v0 = ls[t][l], v1 = ls[t][l + 32];
        float mx = fmaxf(v0, v1);
#pragma unroll
        for (int o = 16; o; o >>= 1) mx = fmaxf(mx, __shfl_xor_sync(0xffffffffu, mx, o));
        float e0 = expf(v0 - mx), e1 = expf(v1 - mx);
        float sm = e0 + e1;
#pragma unroll
        for (int o = 16; o; o >>= 1) sm += __shfl_xor_sync(0xffffffffu, sm, o);
        float inv = 1.0f / sm;
        pi_out[(size_t)(t0 + t) * Vn + l] = e0 * inv;
        pi_out[(size_t)(t0 + t) * Vn + l + 32] = e1 * inv;
    }
}

// ---------------------------------------------------------------------------
// Per-token Q assembly (theta has padded row stride NTp)
// ---------------------------------------------------------------------------
__global__ __launch_bounds__(256)
void q_kernel(const float* __restrict__ theta, const float* __restrict__ pi,
              float* __restrict__ qout) {
    const int t = blockIdx.x;
    const int tid = threadIdx.x;
    __shared__ float th[NTn];
    __shared__ float sp[Vn], rp[Vn];
    __shared__ float qs[Vn][Vn + 1];
    __shared__ float rsum[Vn][4];

    const float4* trow = (const float4*)(theta + (size_t)t * NTp);
    for (int i = tid; i < NTn / 4; i += 256) ((float4*)th)[i] = trow[i];
    if (tid < Vn) {
        float p = pi[(size_t)t * Vn + tid];
        float s = sqrtf(p);
        sp[tid] = s;
        rp[tid] = 1.0f / s;
    }
    __syncthreads();

    const int i = tid >> 2, c = tid & 3;
    const float ri = rp[i];
    float part = 0.0f;
#pragma unroll
    for (int jj = 0; jj < 16; jj++) {
        const int j = c + jj * 4;
        float q = 0.0f;
        if (j != i) {
            const int a = min(i, j), b = max(i, j);
            const int k = a * 63 - (a * (a - 1)) / 2 + (b - a - 1);
            q = th[k] * sp[j] * ri;
        }
        qs[i][j] = q;
        part += q;
    }
    rsum[i][c] = part;
    __syncthreads();
    if (c == 0) {
        qs[i][i] = -(rsum[i][0] + rsum[i][1] + rsum[i][2] + rsum[i][3]);
    }
    __syncthreads();

    float* o = qout + (size_t)t * Vn * Vn;
#pragma unroll
    for (int r = 0; r < 4; r++) {
        const int e4 = tid + r * 256;
        const int e = e4 * 4;
        const int ii = e >> 6, j = e & 63;
        float4 v = make_float4(qs[ii][j], qs[ii][j + 1], qs[ii][j + 2], qs[ii][j + 3]);
        ((float4*)o)[e4] = v;
    }
}

// ---------------------------------------------------------------------------
extern "C" void kernel_launch(void* const* d_in, const int* in_sizes, int n_in,
                              void* d_out, int out_size) {
    const float* hx = (const float*)d_in[0];
    const float* Wd = (const float*)d_in[1];
    const float* bd = (const float*)d_in[2];
    const float* lng = (const float*)d_in[3];
    const float* lnb = (const float*)d_in[4];
    const float* Wt = (const float*)d_in[5];
    const float* bt = (const float*)d_in[6];
    const float* WT = (const float*)d_in[7];
    const float* bT = (const float*)d_in[8];

    float* out = (float*)d_out;
    float* qout = out;                                  // (B,L,V,V)
    float* piout = out + (size_t)Mn * Vn * Vn;          // (B,L,V)

    void* p;
    cudaGetSymbolAddress(&p, g_hx_hi);  __half* hxh = (__half*)p;
    cudaGetSymbolAddress(&p, g_Wd_hi);  __half* wdh = (__half*)p;
    cudaGetSymbolAddress(&p, g_Wd_lo);  __half* wdl = (__half*)p;
    cudaGetSymbolAddress(&p, g_WT_hi);  __half* wth = (__half*)p;
    cudaGetSymbolAddress(&p, g_WT_lo);  __half* wtl = (__half*)p;
    cudaGetSymbolAddress(&p, g_H_hi);   __half* hh = (__half*)p;
    cudaGetSymbolAddress(&p, g_act);    float* gact = (float*)p;
    cudaGetSymbolAddress(&p, g_hidden); float* gh = (float*)p;
    cudaGetSymbolAddress(&p, g_theta);  float* gth = (float*)p;

    cudaFuncSetAttribute(gemm_mma_kernel<1>, cudaFuncAttributeMaxDynamicSharedMemorySize,
                         gm::SMEM_BYTES);
    cudaFuncSetAttribute(gemm_mma_kernel<2>, cudaFuncAttributeMaxDynamicSharedMemorySize,
                         gm::SMEM_BYTES);

    dim3 blk(256);

    // 0) conversions: A side hi-only; B side hi+lo
    cvt_hi_kernel<<<2048, blk>>>(hx, hxh, Mn * En / 4);
    cvt_split_kernel<<<1024, blk>>>(Wd, wdh, wdl, En * En / 4);
    cvt_split_pad_kernel<<<1024, blk>>>(WT, wth, wtl, NTn, NTp, En);

    // 1) dense + gelu  (M=8192, N=1024)
    {
        dim3 grid(En / 128, Mn / 128);  // (8, 64)
        gemm_mma_kernel<1><<<grid, blk, gm::SMEM_BYTES>>>(hxh, wdh, wdl, bd, gact,
                                                          En, En);
    }

    // 2) LayerNorm + f16-hi
    ln_split_kernel<<<Mn, blk>>>(gact, gh, hh, lng, lnb);

    // 3) logits + softmax -> pi (written directly into output)
    pi_softmax_kernel<<<Mn / 64, blk>>>(gh, Wt, bt, piout);

    // 4) Theta projection + softplus (M=8192, Npad=2048)
    {
        dim3 grid(NTp / 128, Mn / 128);  // (16, 64)
        gemm_mma_kernel<2><<<grid, blk, gm::SMEM_BYTES>>>(hh, wth, wtl, bT, gth,
                                                          NTn, NTp);
    }

    // 5) Q assembly
    q_kernel<<<Mn, blk>>>(gth, piout, qout);
}

// round 17
// speedup vs baseline: 3.0619x; 1.0343x over previous
#include <cuda_runtime.h>
#include <cuda_fp16.h>
#include <math.h>
#include <stdint.h>

// ---------------------------------------------------------------------------
// Problem constants
// ---------------------------------------------------------------------------
namespace {
constexpr int Bn = 4, Ln = 2048, En = 1024, Vn = 64, NTn = 2016;
constexpr int Mn = Bn * Ln;          // 8192 tokens
constexpr int NTp = 2048;            // padded Theta output dim
}

// ---------------------------------------------------------------------------
// Scratch (static device globals — no runtime allocation)
// ---------------------------------------------------------------------------
__device__ __half g_hx_hi[(size_t)Mn * En];
__device__ __half g_Wd_hi[(size_t)En * En];
__device__ __half g_Wd_lo[(size_t)En * En];
__device__ __half g_WT_hi[(size_t)NTp * En];   // padded, rows >=2016 zero
__device__ __half g_WT_lo[(size_t)NTp * En];
__device__ __half g_H_hi[(size_t)Mn * En];
__device__ float g_act[(size_t)Mn * En];      // gelu(dense) output f32
__device__ float g_theta[(size_t)Mn * NTp];   // softplus(Theta), padded stride

__device__ __forceinline__ float gelu_exact(float x) {
    return 0.5f * x * (1.0f + erff(x * 0.7071067811865476f));
}
__device__ __forceinline__ float softplus_f(float x) {
    if (x > 20.0f) return x;
    return log1pf(expf(x));
}

__device__ __forceinline__ uint32_t smem_to_u32(const void* p) {
    uint32_t a;
    asm("{ .reg .u64 t; cvta.to.shared.u64 t, %1; cvt.u32.u64 %0, t; }"
        : "=r"(a) : "l"(p));
    return a;
}

// ---------------------------------------------------------------------------
// mma.sync / ldmatrix / cp.async primitives (plain sm_80+ PTX, no 'a' features)
// ---------------------------------------------------------------------------
__device__ __forceinline__ void mma16816(float c[4], const uint32_t a[4],
                                         uint32_t b0, uint32_t b1) {
    asm volatile(
        "mma.sync.aligned.m16n8k16.row.col.f32.f16.f16.f32 "
        "{%0,%1,%2,%3}, {%4,%5,%6,%7}, {%8,%9}, {%0,%1,%2,%3};"
        : "+f"(c[0]), "+f"(c[1]), "+f"(c[2]), "+f"(c[3])
        : "r"(a[0]), "r"(a[1]), "r"(a[2]), "r"(a[3]), "r"(b0), "r"(b1));
}

__device__ __forceinline__ void ldm_x4(uint32_t r[4], uint32_t addr) {
    asm volatile("ldmatrix.sync.aligned.m8n8.x4.shared.b16 {%0,%1,%2,%3}, [%4];"
        : "=r"(r[0]), "=r"(r[1]), "=r"(r[2]), "=r"(r[3]) : "r"(addr));
}

__device__ __forceinline__ void cp16(uint32_t s, const void* g) {
    asm volatile("cp.async.cg.shared.global [%0], [%1], 16;" :: "r"(s), "l"(g));
}
#define CP_COMMIT() asm volatile("cp.async.commit_group;" ::: "memory")
#define CP_WAIT2()  asm volatile("cp.async.wait_group 2;" ::: "memory")
#define CP_WAIT1()  asm volatile("cp.async.wait_group 1;" ::: "memory")
#define CP_WAIT0()  asm volatile("cp.async.wait_group 0;" ::: "memory")

// ---------------------------------------------------------------------------
// Split conversion: f32 -> f16 hi (+ f16 lo)
// ---------------------------------------------------------------------------
__device__ __forceinline__ void split1h(float v, __half& h, __half& l) {
    h = __float2half(v);
    l = __float2half(v - __half2float(h));
}

__global__ __launch_bounds__(256)
void cvt_hi_kernel(const float* __restrict__ src, __half* __restrict__ hi, int n4) {
    for (int i = blockIdx.x * 256 + threadIdx.x; i < n4; i += gridDim.x * 256) {
        float4 v = ((const float4*)src)[i];
        __half h[4];
        h[0] = __float2half(v.x); h[1] = __float2half(v.y);
        h[2] = __float2half(v.z); h[3] = __float2half(v.w);
        ((uint2*)hi)[i] = *(uint2*)h;
    }
}

__global__ __launch_bounds__(256)
void cvt_split_kernel(const float* __restrict__ src, __half* __restrict__ hi,
                      __half* __restrict__ lo, int n4) {
    for (int i = blockIdx.x * 256 + threadIdx.x; i < n4; i += gridDim.x * 256) {
        float4 v = ((const float4*)src)[i];
        __half h[4], l[4];
        split1h(v.x, h[0], l[0]); split1h(v.y, h[1], l[1]);
        split1h(v.z, h[2], l[2]); split1h(v.w, h[3], l[3]);
        ((uint2*)hi)[i] = *(uint2*)h;
        ((uint2*)lo)[i] = *(uint2*)l;
    }
}

// padded variant: rows >= rows_real are zero (cols multiple of 4)
__global__ __launch_bounds__(256)
void cvt_split_pad_kernel(const float* __restrict__ src, __half* __restrict__ hi,
                          __half* __restrict__ lo, int rows_real, int rows_pad,
                          int cols) {
    int n4 = rows_pad * cols / 4;
    int c4 = cols / 4;
    for (int i = blockIdx.x * 256 + threadIdx.x; i < n4; i += gridDim.x * 256) {
        int row = i / c4;
        float4 v = make_float4(0.f, 0.f, 0.f, 0.f);
        if (row < rows_real) {
            int col4 = i - row * c4;
            v = ((const float4*)src)[(size_t)row * c4 + col4];
        }
        __half h[4], l[4];
        split1h(v.x, h[0], l[0]); split1h(v.y, h[1], l[1]);
        split1h(v.z, h[2], l[2]); split1h(v.w, h[3], l[3]);
        ((uint2*)hi)[i] = *(uint2*)h;
        ((uint2*)lo)[i] = *(uint2*)l;
    }
}

// ---------------------------------------------------------------------------
// Split-fp16 HMMA GEMM:  C[m,n] = act( sum_k A[m,k]*B[n,k] + bias[n] )
// A: M x 1024 (f16 hi only), B: Npad x 1024 (f16 hi/lo). CTA tile 128x64,
// warp tile 32x32, BK=32, 4-stage cp.async pipeline (depth-3 prefetch),
// 3 CTAs/SM (24 warps), swizzled 64B smem rows. Terms: ah*bh + ah*bl.
// ---------------------------------------------------------------------------
namespace gm {
constexpr int ROWB = 64;             // 32 f16, XOR-swizzled 16B chunks
constexpr int A_TILE = 128 * ROWB;   // 8192 B
constexpr int B_TILE = 64 * ROWB;    // 4096 B
constexpr int OFF_BH = A_TILE;           // 8192
constexpr int OFF_BL = A_TILE + B_TILE;  // 12288
constexpr int STAGE = A_TILE + 2 * B_TILE;  // 16384
constexpr int NSTG = 4;
constexpr int SMEM_BYTES = NSTG * STAGE;    // 65536
constexpr int NKT = 32;              // 1024 / 32
}

// swizzled byte offset within a (rows x 64B) subtile
__device__ __forceinline__ uint32_t swz(uint32_t row, uint32_t ch) {
    return row * 64u + ((ch ^ ((row >> 1) & 3u)) << 4);
}

template <int ACT>  // 1 gelu, 2 softplus
__global__ __launch_bounds__(256, 3)
void gemm_mma_kernel(const __half* __restrict__ Ah,
                     const __half* __restrict__ Bh, const __half* __restrict__ Bl,
                     const float* __restrict__ bias, float* __restrict__ C,
                     int Nreal, int strideN) {
    extern __shared__ char smem[];
    const uint32_t sb = smem_to_u32(smem);
    const int tid = threadIdx.x, wid = tid >> 5, lane = tid & 31;
    const int m0 = blockIdx.y * 128, n0 = blockIdx.x * 64;
    const int wm = (wid & 3) * 32, wn = (wid >> 2) * 32;

    // per-thread copy slots: 4 x 16B per tile
    //  r=0,1: A rows (512 chunks); r=2: Bh (256); r=3: Bl (256)
    uint32_t cp_sa[4];
    const __half* cp_g[4];
#pragma unroll
    for (int r = 0; r < 4; r++) {
        int idx = r * 256 + tid;
        uint32_t row, ch = idx & 3;
        if (r < 2) {
            row = (uint32_t)(idx >> 2);               // 0..127
            cp_g[r] = Ah + (size_t)(m0 + row) * 1024 + ch * 8;
            cp_sa[r] = sb + swz(row, ch);
        } else {
            row = (uint32_t)((idx >> 2) & 63);        // 0..63
            const __half* src = (r == 2) ? Bh : Bl;
            cp_g[r] = src + (size_t)(n0 + row) * 1024 + ch * 8;
            cp_sa[r] = sb + (r == 2 ? gm::OFF_BH : gm::OFF_BL) + swz(row, ch);
        }
    }
    auto copy_stage = [&](int kt, int s) {
        const int kb = kt * 32;
        const uint32_t so = (uint32_t)s * gm::STAGE;
#pragma unroll
        for (int r = 0; r < 4; r++) cp16(cp_sa[r] + so, cp_g[r] + kb);
    };

    // per-warp ldmatrix addressing
    const uint32_t hi16 = (lane >> 4);         // 0/1: +16B within k16 slice
    uint32_t a_off[2][2], b_off[2][2];
#pragma unroll
    for (int mi = 0; mi < 2; mi++) {
        uint32_t row = (uint32_t)(wm + mi * 16 + (lane & 15));
#pragma unroll
        for (int ks = 0; ks < 2; ks++)
            a_off[ks][mi] = swz(row, ks * 2 + hi16);
    }
#pragma unroll
    for (int g = 0; g < 2; g++) {
        uint32_t row = (uint32_t)(wn + g * 16 + ((lane >> 3) & 1) * 8 + (lane & 7));
#pragma unroll
        for (int ks = 0; ks < 2; ks++)
            b_off[ks][g] = swz(row, ks * 2 + hi16);
    }

    float acc[2][4][4];
#pragma unroll
    for (int mi = 0; mi < 2; mi++)
#pragma unroll
        for (int ni = 0; ni < 4; ni++)
#pragma unroll
            for (int e = 0; e < 4; e++) acc[mi][ni][e] = 0.0f;

    copy_stage(0, 0); CP_COMMIT();
    copy_stage(1, 1); CP_COMMIT();
    copy_stage(2, 2); CP_COMMIT();

    int scur = 0;
    for (int kt = 0; kt < gm::NKT; kt++) {
        const int rem = gm::NKT - 1 - kt;
        if (rem >= 2) { CP_WAIT2(); }
        else if (rem == 1) { CP_WAIT1(); }
        else { CP_WAIT0(); }
        __syncthreads();  // copies for kt visible; compute kt-1 done by all
        if (kt + 3 < gm::NKT) {
            copy_stage(kt + 3, (kt + 3) & 3);  // that stage's compute is done
            CP_COMMIT();
        }

        const uint32_t As = sb + (uint32_t)scur * gm::STAGE;
        const uint32_t Bhs = As + gm::OFF_BH;
        const uint32_t Bls = As + gm::OFF_BL;
        if (++scur == gm::NSTG) scur = 0;

#pragma unroll
        for (int ks = 0; ks < 2; ks++) {       // two k16 slices
            uint32_t ah[2][4], bh[2][4], bl[2][4];
#pragma unroll
            for (int mi = 0; mi < 2; mi++) ldm_x4(ah[mi], As + a_off[ks][mi]);
#pragma unroll
            for (int g = 0; g < 2; g++) {
                ldm_x4(bh[g], Bhs + b_off[ks][g]);
                ldm_x4(bl[g], Bls + b_off[ks][g]);
            }
            // Pass 1: hi*hi over 8 independent accumulators
#pragma unroll
            for (int mi = 0; mi < 2; mi++)
#pragma unroll
                for (int ni = 0; ni < 4; ni++) {
                    const int g = ni >> 1, u = ni & 1;
                    mma16816(acc[mi][ni], ah[mi], bh[g][u], bh[g][u + 2]);
                }
            // Pass 2: hi*lo
#pragma unroll
            for (int mi = 0; mi < 2; mi++)
#pragma unroll
                for (int ni = 0; ni < 4; ni++) {
                    const int g = ni >> 1, u = ni & 1;
                    mma16816(acc[mi][ni], ah[mi], bl[g][u], bl[g][u + 2]);
                }
        }
    }

    // epilogue: bias + activation + float2 stores
    const int rr = lane >> 2, cc = (lane & 3) * 2;
#pragma unroll
    for (int mi = 0; mi < 2; mi++) {
        const int m = m0 + wm + mi * 16 + rr;
#pragma unroll
        for (int ni = 0; ni < 4; ni++) {
            const int n = n0 + wn + ni * 8 + cc;
            float b0v = (n < Nreal) ? bias[n] : 0.0f;
            float b1v = (n + 1 < Nreal) ? bias[n + 1] : 0.0f;
            float v0 = acc[mi][ni][0] + b0v;
            float v1 = acc[mi][ni][1] + b1v;
            float v2 = acc[mi][ni][2] + b0v;
            float v3 = acc[mi][ni][3] + b1v;
            if (ACT == 1) {
                v0 = gelu_exact(v0); v1 = gelu_exact(v1);
                v2 = gelu_exact(v2); v3 = gelu_exact(v3);
            } else {
                v0 = softplus_f(v0); v1 = softplus_f(v1);
                v2 = softplus_f(v2); v3 = softplus_f(v3);
            }
            float2 p0 = make_float2(v0, v1);
            float2 p1 = make_float2(v2, v3);
            *(float2*)&C[(size_t)m * strideN + n] = p0;
            *(float2*)&C[(size_t)(m + 8) * strideN + n] = p1;
        }
    }
}

// ---------------------------------------------------------------------------
// Row LayerNorm over E=1024, f16 output only (feeds pi head + Theta GEMM A).
// ---------------------------------------------------------------------------
__global__ __launch_bounds__(256)
void ln_split_kernel(const float* __restrict__ X, __half* __restrict__ Yhi,
                     const float* __restrict__ gamma, const float* __restrict__ beta) {
    const int row = blockIdx.x;
    const int tid = threadIdx.x;
    const float4* x = (const float4*)(X + (size_t)row * En);

    float4 v = x[tid];
    float s = v.x + v.y + v.z + v.w;
    float s2 = v.x * v.x + v.y * v.y + v.z * v.z + v.w * v.w;
#pragma unroll
    for (int o = 16; o; o >>= 1) {
        s += __shfl_xor_sync(0xffffffffu, s, o);
        s2 += __shfl_xor_sync(0xffffffffu, s2, o);
    }
    __shared__ float rs[8], rs2[8];
    __shared__ float smu, sinv;
    const int w = tid >> 5, l = tid & 31;
    if (l == 0) { rs[w] = s; rs2[w] = s2; }
    __syncthreads();
    if (tid == 0) {
        float a = 0.f, b = 0.f;
#pragma unroll
        for (int i = 0; i < 8; i++) { a += rs[i]; b += rs2[i]; }
        float mu = a * (1.0f / En);
        float var = b * (1.0f / En) - mu * mu;
        smu = mu;
        sinv = rsqrtf(var + 1e-5f);
    }
    __syncthreads();
    const float mu = smu, inv = sinv;
    float4 g4 = ((const float4*)gamma)[tid];
    float4 b4 = ((const float4*)beta)[tid];
    __half h[4];
    h[0] = __float2half((v.x - mu) * inv * g4.x + b4.x);
    h[1] = __float2half((v.y - mu) * inv * g4.y + b4.y);
    h[2] = __float2half((v.z - mu) * inv * g4.z + b4.z);
    h[3] = __float2half((v.w - mu) * inv * g4.w + b4.w);
    ((uint2*)(Yhi + (size_t)row * En))[tid] = *(uint2*)h;
}

// ---------------------------------------------------------------------------
// Fused logits GEMM (64 tokens x 64 outputs, K=1024) + softmax -> pi.
// H is f16 (hi part); W stays f32.
// ---------------------------------------------------------------------------
__global__ __launch_bounds__(256)
void pi_softmax_kernel(const __half* __restrict__ H, const float* __restrict__ Wt,
                       const float* __restrict__ bt, float* __restrict__ pi_out) {
    constexpr int TM = 64, TK = 32, PAD = 4;
    __shared__ float hs[TK][TM + PAD];
    __shared__ float ws[TK][TM + PAD];
    __shared__ float ls[64][65];

    const int t0 = blockIdx.x * TM;
    const int tid = threadIdx.x;
    const int tx = tid & 15, ty = tid >> 4;
    const int r0 = tid >> 3;          // 0..31 (w loads)
    const int c4 = (tid & 7) * 4;     // 0..28
    const int hrow = tid >> 2;        // 0..63 (h loads)
    const int hc8 = (tid & 3) * 8;    // 0..24

    float acc[4][4];
#pragma unroll
    for (int i = 0; i < 4; i++)
#pragma unroll
        for (int j = 0; j < 4; j++) acc[i][j] = 0.0f;

    for (int kt = 0; kt < En / TK; kt++) {
        const int kb = kt * TK;
        // H: 64 rows x 32 k (f16) -> one uint4 (8 halfs) per thread
        uint4 hv = *(const uint4*)&H[(size_t)(t0 + hrow) * En + kb + hc8];
        float4 w0 = *(const float4*)&Wt[(size_t)r0 * En + kb + c4];
        float4 w1 = *(const float4*)&Wt[(size_t)(r0 + 32) * En + kb + c4];
        __syncthreads();
        {
            const __half2* hp = (const __half2*)&hv;
#pragma unroll
            for (int q = 0; q < 4; q++) {
                float2 f = __half22float2(hp[q]);
                hs[hc8 + q * 2 + 0][hrow] = f.x;
                hs[hc8 + q * 2 + 1][hrow] = f.y;
            }
        }
        ws[c4 + 0][r0] = w0.x; ws[c4 + 1][r0] = w0.y; ws[c4 + 2][r0] = w0.z; ws[c4 + 3][r0] = w0.w;
        ws[c4 + 0][r0 + 32] = w1.x; ws[c4 + 1][r0 + 32] = w1.y; ws[c4 + 2][r0 + 32] = w1.z; ws[c4 + 3][r0 + 32] = w1.w;
        __syncthreads();
#pragma unroll
        for (int k = 0; k < TK; k++) {
            float a[4], b[4];
            *(float4*)a = *(const float4*)&hs[k][ty * 4];
            *(float4*)b = *(const float4*)&ws[k][tx * 4];
#pragma unroll
            for (int i = 0; i < 4; i++)
#pragma unroll
                for (int j = 0; j < 4; j++)
                    acc[i][j] = fmaf(a[i], b[j], acc[i][j]);
        }
    }
    __syncthreads();
#pragma unroll
    for (int i = 0; i < 4; i++)
#pragma unroll
        for (int j = 0; j < 4; j++)
            ls[ty * 4 + i][tx * 4 + j] = acc[i][j] + bt[tx * 4 + j];
    __syncthreads();

    const int w = tid >> 5, l = tid & 31;
    for (int t = w; t < 64; t += 8) {
        float v0 = ls[t][l], v1 = ls[t][l + 32];
        float mx = fmaxf(v0, v1);
#pragma unroll
        for (int o = 16; o; o >>= 1) mx = fmaxf(mx, __shfl_xor_sync(0xffffffffu, mx, o));
        float e0 = expf(v0 - mx), e1 = expf(v1 - mx);
        float sm = e0 + e1;
#pragma unroll
        for (int o = 16; o; o >>= 1) sm += __shfl_xor_sync(0xffffffffu, sm, o);
        float inv = 1.0f / sm;
        pi_out[(size_t)(t0 + t) * Vn + l] = e0 * inv;
        pi_out[(size_t)(t0 + t) * Vn + l + 32] = e1 * inv;
    }
}

// ---------------------------------------------------------------------------
// Per-token Q assembly (theta has padded row stride NTp)
// ---------------------------------------------------------------------------
__global__ __launch_bounds__(256)
void q_kernel(const float* __restrict__ theta, const float* __restrict__ pi,
              float* __restrict__ qout) {
    const int t = blockIdx.x;
    const int tid = threadIdx.x;
    __shared__ float th[NTn];
    __shared__ float sp[Vn], rp[Vn];
    __shared__ float qs[Vn][Vn + 1];
    __shared__ float rsum[Vn][4];

    const float4* trow = (const float4*)(theta + (size_t)t * NTp);
    for (int i = tid; i < NTn / 4; i += 256) ((float4*)th)[i] = trow[i];
    if (tid < Vn) {
        float p = pi[(size_t)t * Vn + tid];
        float s = sqrtf(p);
        sp[tid] = s;
        rp[tid] = 1.0f / s;
    }
    __syncthreads();

    const int i = tid >> 2, c = tid & 3;
    const float ri = rp[i];
    float part = 0.0f;
#pragma unroll
    for (int jj = 0; jj < 16; jj++) {
        const int j = c + jj * 4;
        float q = 0.0f;
        if (j != i) {
            const int a = min(i, j), b = max(i, j);
            const int k = a * 63 - (a * (a - 1)) / 2 + (b - a - 1);
            q = th[k] * sp[j] * ri;
        }
        qs[i][j] = q;
        part += q;
    }
    rsum[i][c] = part;
    __syncthreads();
    if (c == 0) {
        qs[i][i] = -(rsum[i][0] + rsum[i][1] + rsum[i][2] + rsum[i][3]);
    }
    __syncthreads();

    float* o = qout + (size_t)t * Vn * Vn;
#pragma unroll
    for (int r = 0; r < 4; r++) {
        const int e4 = tid + r * 256;
        const int e = e4 * 4;
        const int ii = e >> 6, j = e & 63;
        float4 v = make_float4(qs[ii][j], qs[ii][j + 1], qs[ii][j + 2], qs[ii][j + 3]);
        ((float4*)o)[e4] = v;
    }
}

// ---------------------------------------------------------------------------
extern "C" void kernel_launch(void* const* d_in, const int* in_sizes, int n_in,
                              void* d_out, int out_size) {
    const float* hx = (const float*)d_in[0];
    const float* Wd = (const float*)d_in[1];
    const float* bd = (const float*)d_in[2];
    const float* lng = (const float*)d_in[3];
    const float* lnb = (const float*)d_in[4];
    const float* Wt = (const float*)d_in[5];
    const float* bt = (const float*)d_in[6];
    const float* WT = (const float*)d_in[7];
    const float* bT = (const float*)d_in[8];

    float* out = (float*)d_out;
    float* qout = out;                                  // (B,L,V,V)
    float* piout = out + (size_t)Mn * Vn * Vn;          // (B,L,V)

    void* p;
    cudaGetSymbolAddress(&p, g_hx_hi);  __half* hxh = (__half*)p;
    cudaGetSymbolAddress(&p, g_Wd_hi);  __half* wdh = (__half*)p;
    cudaGetSymbolAddress(&p, g_Wd_lo);  __half* wdl = (__half*)p;
    cudaGetSymbolAddress(&p, g_WT_hi);  __half* wth = (__half*)p;
    cudaGetSymbolAddress(&p, g_WT_lo);  __half* wtl = (__half*)p;
    cudaGetSymbolAddress(&p, g_H_hi);   __half* hh = (__half*)p;
    cudaGetSymbolAddress(&p, g_act);    float* gact = (float*)p;
    cudaGetSymbolAddress(&p, g_theta);  float* gth = (float*)p;

    cudaFuncSetAttribute(gemm_mma_kernel<1>, cudaFuncAttributeMaxDynamicSharedMemorySize,
                         gm::SMEM_BYTES);
    cudaFuncSetAttribute(gemm_mma_kernel<2>, cudaFuncAttributeMaxDynamicSharedMemorySize,
                         gm::SMEM_BYTES);

    dim3 blk(256);

    // 0) conversions: A side hi-only; B side hi+lo
    cvt_hi_kernel<<<2048, blk>>>(hx, hxh, Mn * En / 4);
    cvt_split_kernel<<<1024, blk>>>(Wd, wdh, wdl, En * En / 4);
    cvt_split_pad_kernel<<<1024, blk>>>(WT, wth, wtl, NTn, NTp, En);

    // 1) dense + gelu  (M=8192, N=1024)
    {
        dim3 grid(En / 64, Mn / 128);  // (16, 64)
        gemm_mma_kernel<1><<<grid, blk, gm::SMEM_BYTES>>>(hxh, wdh, wdl, bd, gact,
                                                          En, En);
    }

    // 2) LayerNorm -> f16 hidden only
    ln_split_kernel<<<Mn, blk>>>(gact, hh, lng, lnb);

    // 3) logits + softmax -> pi (written directly into output)
    pi_softmax_kernel<<<Mn / 64, blk>>>(hh, Wt, bt, piout);

    // 4) Theta projection + softplus (M=8192, Npad=2048)
    {
        dim3 grid(NTp / 64, Mn / 128);  // (32, 64)
        gemm_mma_kernel<2><<<grid, blk, gm::SMEM_BYTES>>>(hh, wth, wtl, bT, gth,
                                                          NTn, NTp);
    }

    // 5) Q assembly
    q_kernel<<<Mn, blk>>>(gth, piout, qout);
}